// round 11
// baseline (speedup 1.0000x reference)
#include <cuda_runtime.h>
#include <cuda_bf16.h>
#include <cstdint>
#include <math.h>

#define N 4096
#define D 1024
#define NUM_NEG 100
#define NT 8             // K=1024 / 128 int8 per stage
#define STAGE_A (128 * 128)           // 16384 bytes (A half)
#define STAGE_BYTES 32768             // A(16K) + B(16K)
#define DSMEM 98304                   // 3 stages

// quantization scales
#define SCALE_Z 512.0f
#define SCALE_W 512.0f
#define SCALE_H 256.0f
#define SCALE_P 512.0f
#define DESC_L1 (1.0f / (SCALE_Z * SCALE_W))
#define DESC_L2 (1.0f / (SCALE_H * SCALE_W))
#define DESC_SIM (1.0f / (SCALE_P * SCALE_P))

// ---------------- scratch (device globals; no allocation allowed) ----------
__device__ uint8_t g_Zall[4 * N * D];          // s8 inputs (stacked, x512)
__device__ uint8_t g_Hall[4 * N * D];          // s8 hidden (x256)
__device__ __nv_bfloat16 g_P[4 * N * D];       // bf16 projections
__device__ uint8_t g_Pq[4 * N * D];            // s8 normalized projections (x512)
__device__ uint8_t g_W1q[D * D];               // s8 weights (x512)
__device__ uint8_t g_W2q[D * D];
__device__ __nv_bfloat16 g_z1[N * D];
__device__ __nv_bfloat16 g_z2[N * D];
__device__ float g_rowsum[N], g_colsum[N], g_mrow[N], g_mcol[N], g_lse[N];
__device__ double g_s[4];  // [0]=gcl1 logsum, [1]=gcl2 logsum, [2]=pair_sum, [3]=pair_cnt

// ---------------- helpers ---------------------------------------------------
__device__ __forceinline__ uint32_t bf2_pack(float a, float b) {
    __nv_bfloat162 t = __floats2bfloat162_rn(a, b);
    return *reinterpret_cast<uint32_t*>(&t);
}

__device__ __forceinline__ int q8(float x) {
    int v = __float2int_rn(x);
    return max(-127, min(127, v));
}

__device__ __forceinline__ uint32_t pack4_s8(float a, float b, float c, float d) {
    return (uint32_t)(q8(a) & 0xFF) | ((uint32_t)(q8(b) & 0xFF) << 8) |
           ((uint32_t)(q8(c) & 0xFF) << 16) | ((uint32_t)(q8(d) & 0xFF) << 24);
}

__device__ __forceinline__ uint16_t pack2_s8(float a, float b) {
    return (uint16_t)((q8(a) & 0xFF) | ((q8(b) & 0xFF) << 8));
}

__device__ __forceinline__ void imma16832(int* c, const uint32_t* a, const uint32_t* b) {
    asm volatile(
        "mma.sync.aligned.m16n8k32.row.col.s32.s8.s8.s32 "
        "{%0,%1,%2,%3}, {%4,%5,%6,%7}, {%8,%9}, {%0,%1,%2,%3};"
        : "+r"(c[0]), "+r"(c[1]), "+r"(c[2]), "+r"(c[3])
        : "r"(a[0]), "r"(a[1]), "r"(a[2]), "r"(a[3]), "r"(b[0]), "r"(b[1]));
}

__device__ __forceinline__ void ldsm4(uint32_t* r, uint32_t saddr) {
    asm volatile("ldmatrix.sync.aligned.m8n8.x4.shared.b16 {%0,%1,%2,%3}, [%4];"
                 : "=r"(r[0]), "=r"(r[1]), "=r"(r[2]), "=r"(r[3]) : "r"(saddr));
}

template <int W>
__device__ __forceinline__ void cpwait() {
    asm volatile("cp.async.wait_group %0;" :: "n"(W));
}

// swizzled byte offset inside a rows x 128B stage tile (16B chunks XOR'd)
__device__ __forceinline__ uint32_t SWZ64(int r, int ch) {
    return (uint32_t)(r * 128 + ((ch ^ (r & 7)) << 4));
}

// load one 128-K s8 stage of A(128 rows) + B(128 rows), 256 threads
__device__ __forceinline__ void ld_stage(
    const uint8_t* __restrict__ A, const uint8_t* __restrict__ B,
    int m0, int n0, int kt, uint32_t st, int tid) {
    #pragma unroll
    for (int i = 0; i < 4; i++) {
        int idx = tid + i * 256;
        int row = idx >> 3, ch = idx & 7;
        const uint8_t* g = &A[(size_t)(m0 + row) * D + kt + ch * 16];
        asm volatile("cp.async.cg.shared.global [%0], [%1], 16;"
                     :: "r"(st + SWZ64(row, ch)), "l"(g));
    }
    #pragma unroll
    for (int i = 0; i < 4; i++) {
        int idx = tid + i * 256;
        int row = idx >> 3, ch = idx & 7;
        const uint8_t* g = &B[(size_t)(n0 + row) * D + kt + ch * 16];
        asm volatile("cp.async.cg.shared.global [%0], [%1], 16;"
                     :: "r"(st + STAGE_A + SWZ64(row, ch)), "l"(g));
    }
}

// ---------------- s8 IMMA NT GEMM (128x128 block, 64x32 per warp, 8 warps)
// C[i,j] = sum_k A[i,k]*B[j,k] (descaled).  MODE 0: +bias+ELU->s8(x256),
// 1: +bias->bf16, 2: sim epilogue (exp, rowsum/colsum + pos-masked mrow/mcol)
template <int MODE>
__global__ __launch_bounds__(256, 2)
void mm_s8_k(const uint8_t* __restrict__ A, const uint8_t* __restrict__ B,
             const float* __restrict__ bias, void* __restrict__ Cout,
             const float* __restrict__ pos,
             float* __restrict__ rowsum, float* __restrict__ colsum,
             float* __restrict__ mrow, float* __restrict__ mcol, int Nc) {
    extern __shared__ __align__(16) char dsm[];
    __shared__ float srow[128], srowm[128];

    int tid = threadIdx.x;
    int warp = tid >> 5, lane = tid & 31;
    int g = lane >> 2, t4 = lane & 3;
    int wm = (warp >> 2) * 64;   // 2 warp-rows x 64
    int wn = (warp & 3) * 32;    // 4 warp-cols x 32
    int m0 = blockIdx.y * 128, n0 = blockIdx.x * 128;
    uint32_t sb = (uint32_t)__cvta_generic_to_shared(dsm);

    int acc[4][4][4] = {};

    ld_stage(A, B, m0, n0, 0, sb, tid);
    asm volatile("cp.async.commit_group;");
    ld_stage(A, B, m0, n0, 128, sb + STAGE_BYTES, tid);
    asm volatile("cp.async.commit_group;");

    int lr = lane & 15, lc = lane >> 4;
    for (int s = 0; s < NT; s++) {
        if (s < NT - 1) cpwait<1>(); else cpwait<0>();
        __syncthreads();
        if (s + 2 < NT) {
            ld_stage(A, B, m0, n0, (s + 2) * 128, sb + ((s + 2) % 3) * STAGE_BYTES, tid);
            asm volatile("cp.async.commit_group;");
        }
        uint32_t ab = sb + (s % 3) * STAGE_BYTES;
        uint32_t bb = ab + STAGE_A;
        #pragma unroll
        for (int ks = 0; ks < 4; ks++) {
            int ch = ks * 2 + lc;
            uint32_t a[4][4], b[2][4];
            #pragma unroll
            for (int mi = 0; mi < 4; mi++)
                ldsm4(a[mi], ab + SWZ64(wm + mi * 16 + lr, ch));
            #pragma unroll
            for (int nb = 0; nb < 2; nb++)
                ldsm4(b[nb], bb + SWZ64(wn + nb * 16 + lr, ch));
            #pragma unroll
            for (int mi = 0; mi < 4; mi++)
                #pragma unroll
                for (int ni = 0; ni < 4; ni++) {
                    uint32_t bf[2] = { b[ni >> 1][ni & 1], b[ni >> 1][(ni & 1) + 2] };
                    imma16832(acc[mi][ni], a[mi], bf);
                }
        }
    }
    __syncthreads();   // smem reuse barrier (MODE 2 epilogue overlays stage bufs)

    if (MODE == 2) {
        if (tid < 128) { srow[tid] = 0.f; srowm[tid] = 0.f; }
        __syncthreads();
        const float ea = 1.25f * DESC_SIM;   // (1/TAU) / (SA*SB)
        float ef[4][4][4];
        float rp[4][2] = {}, rpm[4][2] = {};
        #pragma unroll
        for (int mi = 0; mi < 4; mi++) {
            int r0 = m0 + wm + mi * 16 + g;
            int r1 = r0 + 8;
            #pragma unroll
            for (int ni = 0; ni < 4; ni++) {
                int c = n0 + wn + ni * 8 + t4 * 2;
                float e0 = __expf((float)acc[mi][ni][0] * ea);
                float e1 = __expf((float)acc[mi][ni][1] * ea);
                float e2 = __expf((float)acc[mi][ni][2] * ea);
                float e3 = __expf((float)acc[mi][ni][3] * ea);
                ef[mi][ni][0] = e0; ef[mi][ni][1] = e1;
                ef[mi][ni][2] = e2; ef[mi][ni][3] = e3;
                float2 p0 = *(const float2*)&pos[(size_t)r0 * N + c];
                float2 p1 = *(const float2*)&pos[(size_t)r1 * N + c];
                rp[mi][0] += e0 + e1;            rp[mi][1] += e2 + e3;
                rpm[mi][0] += e0 * p0.x + e1 * p0.y;
                rpm[mi][1] += e2 * p1.x + e3 * p1.y;
            }
        }
        #pragma unroll
        for (int mi = 0; mi < 4; mi++) {
            int r = wm + mi * 16 + g;
            atomicAdd(&srow[r], rp[mi][0]);
            atomicAdd(&srow[r + 8], rp[mi][1]);
            atomicAdd(&srowm[r], rpm[mi][0]);
            atomicAdd(&srowm[r + 8], rpm[mi][1]);
        }
        // transpose e-tile into smem: et[col_local][row_local], pitch 65
        float* et = (float*)dsm + warp * (32 * 65);
        #pragma unroll
        for (int mi = 0; mi < 4; mi++)
            #pragma unroll
            for (int ni = 0; ni < 4; ni++)
                #pragma unroll
                for (int q = 0; q < 4; q++) {
                    int rl = mi * 16 + g + ((q >= 2) ? 8 : 0);
                    int cl = ni * 8 + t4 * 2 + (q & 1);
                    et[cl * 65 + rl] = ef[mi][ni][q];
                }
        __syncwarp();
        // lane owns one column; pos column read is contiguous
        int c = n0 + wn + lane;
        const float4* pc = (const float4*)&pos[(size_t)c * N + m0 + wm];
        float cs = 0.f, csm = 0.f;
        #pragma unroll
        for (int q = 0; q < 16; q++) {
            float4 m4 = pc[q];
            float a0 = et[lane * 65 + q * 4 + 0];
            float a1 = et[lane * 65 + q * 4 + 1];
            float a2 = et[lane * 65 + q * 4 + 2];
            float a3 = et[lane * 65 + q * 4 + 3];
            cs  += a0 + a1 + a2 + a3;
            csm += a0 * m4.x + a1 * m4.y + a2 * m4.z + a3 * m4.w;
        }
        atomicAdd(&colsum[c], cs);
        atomicAdd(&mcol[c], csm);
        __syncthreads();
        if (tid < 128) {
            atomicAdd(&rowsum[m0 + tid], srow[tid]);
            atomicAdd(&mrow[m0 + tid], srowm[tid]);
        }
    } else {
        const float dsc = (MODE == 0) ? DESC_L1 : DESC_L2;
        #pragma unroll
        for (int mi = 0; mi < 4; mi++) {
            int r0 = m0 + wm + mi * 16 + g;
            #pragma unroll
            for (int ni = 0; ni < 4; ni++) {
                int c = n0 + wn + ni * 8 + t4 * 2;
                float2 bc = *(const float2*)&bias[c];
                float v0 = (float)acc[mi][ni][0] * dsc + bc.x;
                float v1 = (float)acc[mi][ni][1] * dsc + bc.y;
                float v2 = (float)acc[mi][ni][2] * dsc + bc.x;
                float v3 = (float)acc[mi][ni][3] * dsc + bc.y;
                if (MODE == 0) {
                    v0 = (v0 > 0.f) ? v0 : expm1f(v0);
                    v1 = (v1 > 0.f) ? v1 : expm1f(v1);
                    v2 = (v2 > 0.f) ? v2 : expm1f(v2);
                    v3 = (v3 > 0.f) ? v3 : expm1f(v3);
                    uint8_t* C = (uint8_t*)Cout;
                    *(uint16_t*)&C[(size_t)r0 * Nc + c] = pack2_s8(v0 * SCALE_H, v1 * SCALE_H);
                    *(uint16_t*)&C[(size_t)(r0 + 8) * Nc + c] = pack2_s8(v2 * SCALE_H, v3 * SCALE_H);
                } else {
                    __nv_bfloat16* C = (__nv_bfloat16*)Cout;
                    *(uint32_t*)&C[(size_t)r0 * Nc + c] = bf2_pack(v0, v1);
                    *(uint32_t*)&C[(size_t)(r0 + 8) * Nc + c] = bf2_pack(v2, v3);
                }
            }
        }
    }
}

// ---------------- small utility kernels ------------------------------------
__global__ void zero_scalars_k(double* s) {
    if (threadIdx.x < 4) s[threadIdx.x] = 0.0;
}

__global__ void zero4_k(float* a, float* b, float* c, float* d) {
    int i = blockIdx.x * blockDim.x + threadIdx.x;
    if (i < N) { a[i] = 0.f; b[i] = 0.f; c[i] = 0.f; d[i] = 0.f; }
}

// float weights -> s8 (x512)
__global__ void conv_w_k(const float* __restrict__ src, uint8_t* __restrict__ dst, int n) {
    int idx = (blockIdx.x * blockDim.x + threadIdx.x) * 4;
    if (idx < n) {
        float4 v = *(const float4*)&src[idx];
        *(uint32_t*)&dst[idx] = pack4_s8(v.x * SCALE_W, v.y * SCALE_W, v.z * SCALE_W, v.w * SCALE_W);
    }
}

// convert 4 inputs to s8 (stacked, x512) AND emit combined bf16 z1/z2
__global__ void conv4_combine_k(const float* __restrict__ a, const float* __restrict__ b,
                                const float* __restrict__ c, const float* __restrict__ d,
                                const float* __restrict__ gamma,
                                uint8_t* __restrict__ dst,
                                __nv_bfloat16* __restrict__ z1, __nv_bfloat16* __restrict__ z2) {
    float gm = *gamma;
    int idx = (blockIdx.x * blockDim.x + threadIdx.x) * 4;
    if (idx < N * D) {
        float4 v0 = *(const float4*)&a[idx];
        float4 v1 = *(const float4*)&b[idx];
        float4 v2 = *(const float4*)&c[idx];
        float4 v3 = *(const float4*)&d[idx];
        *(uint32_t*)&dst[idx] =
            pack4_s8(v0.x * SCALE_Z, v0.y * SCALE_Z, v0.z * SCALE_Z, v0.w * SCALE_Z);
        *(uint32_t*)&dst[(size_t)N * D + idx] =
            pack4_s8(v1.x * SCALE_Z, v1.y * SCALE_Z, v1.z * SCALE_Z, v1.w * SCALE_Z);
        *(uint32_t*)&dst[(size_t)2 * N * D + idx] =
            pack4_s8(v2.x * SCALE_Z, v2.y * SCALE_Z, v2.z * SCALE_Z, v2.w * SCALE_Z);
        *(uint32_t*)&dst[(size_t)3 * N * D + idx] =
            pack4_s8(v3.x * SCALE_Z, v3.y * SCALE_Z, v3.z * SCALE_Z, v3.w * SCALE_Z);
        float og = 1.f - gm;
        *(__nv_bfloat162*)&z1[idx]     = __floats2bfloat162_rn(og*v0.x + gm*v1.x, og*v0.y + gm*v1.y);
        *(__nv_bfloat162*)&z1[idx + 2] = __floats2bfloat162_rn(og*v0.z + gm*v1.z, og*v0.w + gm*v1.w);
        *(__nv_bfloat162*)&z2[idx]     = __floats2bfloat162_rn(og*v2.x + gm*v3.x, og*v2.y + gm*v3.y);
        *(__nv_bfloat162*)&z2[idx + 2] = __floats2bfloat162_rn(og*v2.z + gm*v3.z, og*v2.w + gm*v3.w);
    }
}

// normalize rows (bf16 in) -> s8 normalized (x512), one warp per row, 4N rows
__global__ void normalize_s8_k(const __nv_bfloat16* __restrict__ P, uint8_t* __restrict__ Q) {
    int row = (blockIdx.x * blockDim.x + threadIdx.x) >> 5;
    int lane = threadIdx.x & 31;
    if (row >= 4 * N) return;
    const __nv_bfloat162* p = (const __nv_bfloat162*)(P + (size_t)row * D);
    uint16_t* q = (uint16_t*)(Q + (size_t)row * D);
    float ss = 0.f;
    float2 v[16];
    #pragma unroll
    for (int u = 0; u < 16; u++) {
        v[u] = __bfloat1622float2(p[lane + u * 32]);
        ss += v[u].x * v[u].x + v[u].y * v[u].y;
    }
    #pragma unroll
    for (int o = 16; o; o >>= 1) ss += __shfl_xor_sync(0xffffffffu, ss, o);
    float inv = rsqrtf(ss) * SCALE_P;
    #pragma unroll
    for (int u = 0; u < 16; u++)
        q[lane + u * 32] = pack2_s8(v[u].x * inv, v[u].y * inv);
}

// ---------------- lori reduction --------------------------------------------
__global__ void lori_reduce_k(const float* __restrict__ mrow, const float* __restrict__ rowsum,
                              const float* __restrict__ mcol, const float* __restrict__ colsum,
                              double* __restrict__ target) {
    __shared__ float sm[8];
    int i = blockIdx.x * blockDim.x + threadIdx.x;
    float v = 0.f;
    if (i < N)
        v = logf(mrow[i]) - logf(rowsum[i] + 1e-8f)
          + logf(mcol[i]) - logf(colsum[i] + 1e-8f);
    #pragma unroll
    for (int o = 16; o; o >>= 1) v += __shfl_xor_sync(0xffffffffu, v, o);
    int lane = threadIdx.x & 31, w = threadIdx.x >> 5;
    if (lane == 0) sm[w] = v;
    __syncthreads();
    if (threadIdx.x < 8) {
        float t = sm[threadIdx.x];
        #pragma unroll
        for (int o = 4; o; o >>= 1) t += __shfl_xor_sync(0xffu, t, o);
        if (threadIdx.x == 0) atomicAdd(target, (double)t);
    }
}

// ---------------- InfoNCE LSE over 100 pseudo-random negatives -------------
__global__ __launch_bounds__(128)
void neg_lse_k(const __nv_bfloat16* __restrict__ z1, const __nv_bfloat16* __restrict__ z2,
               const float* __restrict__ md, float* __restrict__ lse) {
    __shared__ float2 zrow[D / 2];
    __shared__ int idxs[NUM_NEG + 32];
    __shared__ float vals[NUM_NEG];
    int i = blockIdx.x;
    const __nv_bfloat162* zi = (const __nv_bfloat162*)(z1 + (size_t)i * D);
    for (int d = threadIdx.x; d < D / 2; d += blockDim.x)
        zrow[d] = __bfloat1622float2(zi[d]);
    int warp = threadIdx.x >> 5, lane = threadIdx.x & 31;
    if (warp == 0) {
        // warp-parallel selection of first NUM_NEG unmasked candidates (t-order)
        const float* mr = md + (size_t)i * N;
        unsigned start = ((unsigned)i * 2654435761u) & (N - 1);
        int cnt = 0;
        unsigned t = 0;
        while (cnt < NUM_NEG) {
            int c = (int)((start + (t + lane) * 97u) & (N - 1));
            float mv = mr[c];
            unsigned bal = __ballot_sync(0xffffffffu, mv == 0.f);
            int prefix = __popc(bal & ((1u << lane) - 1));
            if (mv == 0.f && cnt + prefix < NUM_NEG + 32) idxs[cnt + prefix] = c;
            cnt += __popc(bal);
            t += 32;
        }
    }
    __syncthreads();
    for (int k = warp; k < NUM_NEG; k += 4) {
        const __nv_bfloat162* zc = (const __nv_bfloat162*)(z2 + (size_t)idxs[k] * D);
        float s = 0.f;
        #pragma unroll 4
        for (int d = lane; d < D / 2; d += 32) {
            float2 x = zrow[d];
            float2 y = __bfloat1622float2(zc[d]);
            s = fmaf(x.x, y.x, s);
            s = fmaf(x.y, y.y, s);
        }
        #pragma unroll
        for (int o = 16; o; o >>= 1) s += __shfl_xor_sync(0xffffffffu, s, o);
        if (lane == 0) vals[k] = s;
    }
    __syncthreads();
    if (threadIdx.x == 0) {
        float m = -1e30f;
        for (int k = 0; k < NUM_NEG; k++) m = fmaxf(m, vals[k]);
        float ss = 0.f;
        for (int k = 0; k < NUM_NEG; k++) ss += __expf((vals[k] - m) * 10.0f);
        lse[i] = m * 10.0f + logf(ss);   // 1/INFONCE_TAU = 10
    }
}

// ---------------- InfoNCE positive pairs (warp per row) --------------------
__global__ void inf_pairs_k(const __nv_bfloat16* __restrict__ z1, const __nv_bfloat16* __restrict__ z2,
                            const float* __restrict__ md, const float* __restrict__ lse,
                            double* __restrict__ s) {
    int warp = (blockIdx.x * blockDim.x + threadIdx.x) >> 5;
    int lane = threadIdx.x & 31;
    if (warp >= N) return;
    int i = warp;
    const float* mr = md + (size_t)i * N;
    const __nv_bfloat162* Zi = (const __nv_bfloat162*)(z1 + (size_t)i * D);
    float2 zi[16];
    #pragma unroll
    for (int u = 0; u < 16; u++) zi[u] = __bfloat1622float2(Zi[lane + u * 32]);
    float L = lse[i];
    float sum = 0.f;
    int cnt = 0;
    for (int jb = 0; jb < N; jb += 32) {
        float pv = mr[jb + lane];
        unsigned mask = __ballot_sync(0xffffffffu, pv > 0.f);
        while (mask) {
            int b = __ffs(mask) - 1;
            mask &= mask - 1;
            int j = jb + b;
            const __nv_bfloat162* Zj = (const __nv_bfloat162*)(z2 + (size_t)j * D);
            float dot = 0.f;
            #pragma unroll
            for (int u = 0; u < 16; u++) {
                float2 y = __bfloat1622float2(Zj[lane + u * 32]);
                dot = fmaf(zi[u].x, y.x, dot);
                dot = fmaf(zi[u].y, y.y, dot);
            }
            #pragma unroll
            for (int o = 16; o; o >>= 1) dot += __shfl_xor_sync(0xffffffffu, dot, o);
            float p = dot * 10.0f;
            float mx = fmaxf(p, L);
            float pp = mx + logf(__expf(p - mx) + __expf(L - mx)) - p;
            sum += pp;
            cnt++;
        }
    }
    if (lane == 0) {
        atomicAdd(&s[2], (double)sum);
        atomicAdd(&s[3], (double)cnt);
    }
}

// ---------------- finalize --------------------------------------------------
__global__ void finalize_k(float* out, const double* s) {
    double gcl = -0.5 * (s[0] + s[1]) / (double)N;
    out[0] = (float)(gcl + s[2] / s[3]);
}

// ---------------- launcher --------------------------------------------------
extern "C" void kernel_launch(void* const* d_in, const int* in_sizes, int n_in,
                              void* d_out, int out_size) {
    const float* z_mp1 = (const float*)d_in[0];
    const float* z_sc1 = (const float*)d_in[1];
    const float* pos1  = (const float*)d_in[2];
    const float* z_mp2 = (const float*)d_in[3];
    const float* z_sc2 = (const float*)d_in[4];
    const float* pos2  = (const float*)d_in[5];
    const float* md    = (const float*)d_in[6];
    const float* gamma = (const float*)d_in[7];
    const float* W1 = (const float*)d_in[8];
    const float* b1 = (const float*)d_in[9];
    const float* W2 = (const float*)d_in[10];
    const float* b2 = (const float*)d_in[11];
    float* out = (float*)d_out;

    uint8_t *gZ, *gH, *gPq, *gW1q, *gW2q;
    __nv_bfloat16 *gP, *gz1, *gz2;
    float *grow, *gcol, *gmr, *gmc, *glse;
    double* gs;
    cudaGetSymbolAddress((void**)&gZ, g_Zall);
    cudaGetSymbolAddress((void**)&gH, g_Hall);
    cudaGetSymbolAddress((void**)&gP, g_P);
    cudaGetSymbolAddress((void**)&gPq, g_Pq);
    cudaGetSymbolAddress((void**)&gW1q, g_W1q);
    cudaGetSymbolAddress((void**)&gW2q, g_W2q);
    cudaGetSymbolAddress((void**)&gz1, g_z1);
    cudaGetSymbolAddress((void**)&gz2, g_z2);
    cudaGetSymbolAddress((void**)&grow, g_rowsum);
    cudaGetSymbolAddress((void**)&gcol, g_colsum);
    cudaGetSymbolAddress((void**)&gmr, g_mrow);
    cudaGetSymbolAddress((void**)&gmc, g_mcol);
    cudaGetSymbolAddress((void**)&glse, g_lse);
    cudaGetSymbolAddress((void**)&gs, g_s);

    cudaFuncSetAttribute(mm_s8_k<0>, cudaFuncAttributeMaxDynamicSharedMemorySize, DSMEM);
    cudaFuncSetAttribute(mm_s8_k<1>, cudaFuncAttributeMaxDynamicSharedMemorySize, DSMEM);
    cudaFuncSetAttribute(mm_s8_k<2>, cudaFuncAttributeMaxDynamicSharedMemorySize, DSMEM);

    zero_scalars_k<<<1, 32>>>(gs);
    conv_w_k<<<(D * D / 4 + 255) / 256, 256>>>(W1, gW1q, D * D);
    conv_w_k<<<(D * D / 4 + 255) / 256, 256>>>(W2, gW2q, D * D);
    conv4_combine_k<<<(N * D / 4 + 255) / 256, 256>>>(z_mp1, z_sc1, z_mp2, z_sc2, gamma, gZ, gz1, gz2);

    // batched projection MLP: layer1 (ELU) then layer2, M = 16384
    dim3 gproj(D / 128, 4 * N / 128);      // (8, 128)
    mm_s8_k<0><<<gproj, 256, DSMEM>>>(gZ, gW1q, b1, gH, nullptr, nullptr, nullptr, nullptr, nullptr, D);
    mm_s8_k<1><<<gproj, 256, DSMEM>>>(gH, gW2q, b2, gP, nullptr, nullptr, nullptr, nullptr, nullptr, D);
    normalize_s8_k<<<4 * N / 8, 256>>>(gP, gPq);

    dim3 gsim(N / 128, N / 128);           // (32, 32)
    const float* poss[2] = {pos1, pos2};
    for (int r = 0; r < 2; r++) {
        zero4_k<<<N / 256, 256>>>(grow, gcol, gmr, gmc);
        mm_s8_k<2><<<gsim, 256, DSMEM>>>(gPq + (size_t)(2 * r) * N * D,
                                         gPq + (size_t)(2 * r + 1) * N * D,
                                         nullptr, nullptr, poss[r],
                                         grow, gcol, gmr, gmc, N);
        lori_reduce_k<<<N / 256, 256>>>(gmr, grow, gmc, gcol, &gs[r]);
    }

    neg_lse_k<<<N, 128>>>(gz1, gz2, md, glse);
    inf_pairs_k<<<N / 8, 256>>>(gz1, gz2, md, glse, gs);
    finalize_k<<<1, 1>>>(out, gs);
}

// round 12
// speedup vs baseline: 1.7294x; 1.7294x over previous
#include <cuda_runtime.h>
#include <cuda_bf16.h>
#include <cstdint>
#include <math.h>

#define N 4096
#define D 1024
#define NUM_NEG 100
#define NT 16            // K=1024 / 64
#define STAGE_BYTES 32768
#define DSMEM 98304      // 3 stages x 32KB (epilogue et overlaps)

// ---------------- scratch (device globals; no allocation allowed) ----------
__device__ __nv_bfloat16 g_Zall[4 * N * D];
__device__ __nv_bfloat16 g_Hall[4 * N * D];
__device__ __nv_bfloat16 g_Pall[4 * N * D];
__device__ __nv_bfloat16 g_W1bf[D * D];
__device__ __nv_bfloat16 g_W2bf[D * D];
__device__ __nv_bfloat16 g_z1[N * D];
__device__ __nv_bfloat16 g_z2[N * D];
__device__ float g_rowsum[N], g_colsum[N], g_mrow[N], g_mcol[N], g_lse[N];
__device__ double g_s[4];  // [0]=gcl1 logsum, [1]=gcl2 logsum, [2]=pair_sum, [3]=pair_cnt

// ---------------- helpers ---------------------------------------------------
__device__ __forceinline__ uint32_t bf2_pack(float a, float b) {
    __nv_bfloat162 t = __floats2bfloat162_rn(a, b);
    return *reinterpret_cast<uint32_t*>(&t);
}

__device__ __forceinline__ void mma16816(float* c, const uint32_t* a, const uint32_t* b) {
    asm volatile(
        "mma.sync.aligned.m16n8k16.row.col.f32.bf16.bf16.f32 "
        "{%0,%1,%2,%3}, {%4,%5,%6,%7}, {%8,%9}, {%0,%1,%2,%3};"
        : "+f"(c[0]), "+f"(c[1]), "+f"(c[2]), "+f"(c[3])
        : "r"(a[0]), "r"(a[1]), "r"(a[2]), "r"(a[3]), "r"(b[0]), "r"(b[1]));
}

__device__ __forceinline__ void ldsm4(uint32_t* r, uint32_t saddr) {
    asm volatile("ldmatrix.sync.aligned.m8n8.x4.shared.b16 {%0,%1,%2,%3}, [%4];"
                 : "=r"(r[0]), "=r"(r[1]), "=r"(r[2]), "=r"(r[3]) : "r"(saddr));
}

template <int W>
__device__ __forceinline__ void cpwait() {
    asm volatile("cp.async.wait_group %0;" :: "n"(W));
}

// swizzled byte offset inside a 128x64 bf16 stage tile (rows of 128B, 16B chunks)
__device__ __forceinline__ uint32_t SWZ64(int r, int ch) {
    return (uint32_t)(r * 128 + ((ch ^ (r & 7)) << 4));
}

// load one 64-K stage of A(128 rows) + B(128 rows), 256 threads
__device__ __forceinline__ void ld_stage(
    const __nv_bfloat16* __restrict__ A, const __nv_bfloat16* __restrict__ B,
    int m0, int n0, int kt, uint32_t st, int tid) {
    #pragma unroll
    for (int i = 0; i < 4; i++) {
        int idx = tid + i * 256;
        int row = idx >> 3, ch = idx & 7;
        const __nv_bfloat16* g = &A[(size_t)(m0 + row) * D + kt + ch * 8];
        asm volatile("cp.async.cg.shared.global [%0], [%1], 16;"
                     :: "r"(st + SWZ64(row, ch)), "l"(g));
    }
    #pragma unroll
    for (int i = 0; i < 4; i++) {
        int idx = tid + i * 256;
        int row = idx >> 3, ch = idx & 7;
        const __nv_bfloat16* g = &B[(size_t)(n0 + row) * D + kt + ch * 8];
        asm volatile("cp.async.cg.shared.global [%0], [%1], 16;"
                     :: "r"(st + 16384 + SWZ64(row, ch)), "l"(g));
    }
}

// ---------------- bf16 HMMA NT GEMM ----------------------------------------
// C[i,j] = sum_k A[i,k]*B[j,k].  MODE 0: +bias+ELU->bf16, 1: +bias->bf16,
// 2: sim epilogue (exp(acc/0.8), rowsum/colsum + pos-masked mrow/mcol)
template <int MODE>
__global__ __launch_bounds__(256, 2)
void mm_bf16_k(const __nv_bfloat16* __restrict__ A, const __nv_bfloat16* __restrict__ B,
               const float* __restrict__ bias, __nv_bfloat16* __restrict__ C,
               const float* __restrict__ pos,
               float* __restrict__ rowsum, float* __restrict__ colsum,
               float* __restrict__ mrow, float* __restrict__ mcol, int Nc) {
    extern __shared__ __align__(16) char dsm[];
    __shared__ float srow[128], srowm[128];

    int tid = threadIdx.x;
    int warp = tid >> 5, lane = tid & 31;
    int g = lane >> 2, t4 = lane & 3;
    int wm = (warp >> 2) * 64;   // 2 warp-rows x 64
    int wn = (warp & 3) * 32;    // 4 warp-cols x 32
    int m0 = blockIdx.y * 128, n0 = blockIdx.x * 128;
    uint32_t sb = (uint32_t)__cvta_generic_to_shared(dsm);

    float acc[4][4][4] = {};

    ld_stage(A, B, m0, n0, 0, sb, tid);
    asm volatile("cp.async.commit_group;");
    ld_stage(A, B, m0, n0, 64, sb + STAGE_BYTES, tid);
    asm volatile("cp.async.commit_group;");

    int lr = lane & 15, lc = lane >> 4;
    for (int s = 0; s < NT; s++) {
        if (s < NT - 1) cpwait<1>(); else cpwait<0>();
        __syncthreads();
        if (s + 2 < NT) {
            ld_stage(A, B, m0, n0, (s + 2) * 64, sb + ((s + 2) % 3) * STAGE_BYTES, tid);
            asm volatile("cp.async.commit_group;");
        }
        uint32_t ab = sb + (s % 3) * STAGE_BYTES;
        uint32_t bb = ab + 16384;
        #pragma unroll
        for (int ks = 0; ks < 4; ks++) {
            int ch = ks * 2 + lc;
            uint32_t a[4][4], b[2][4];
            #pragma unroll
            for (int mi = 0; mi < 4; mi++)
                ldsm4(a[mi], ab + SWZ64(wm + mi * 16 + lr, ch));
            #pragma unroll
            for (int nb = 0; nb < 2; nb++)
                ldsm4(b[nb], bb + SWZ64(wn + nb * 16 + lr, ch));
            #pragma unroll
            for (int mi = 0; mi < 4; mi++)
                #pragma unroll
                for (int ni = 0; ni < 4; ni++) {
                    uint32_t bf[2] = { b[ni >> 1][ni & 1], b[ni >> 1][(ni & 1) + 2] };
                    mma16816(acc[mi][ni], a[mi], bf);
                }
        }
    }
    __syncthreads();   // smem reuse barrier (MODE 2 epilogue overlays stage bufs)

    if (MODE == 2) {
        if (tid < 128) { srow[tid] = 0.f; srowm[tid] = 0.f; }
        __syncthreads();
        float rp[4][2] = {}, rpm[4][2] = {};
        #pragma unroll
        for (int mi = 0; mi < 4; mi++) {
            int r0 = m0 + wm + mi * 16 + g;
            int r1 = r0 + 8;
            #pragma unroll
            for (int ni = 0; ni < 4; ni++) {
                int c = n0 + wn + ni * 8 + t4 * 2;
                float e0 = __expf(acc[mi][ni][0] * 1.25f);   // 1/TAU
                float e1 = __expf(acc[mi][ni][1] * 1.25f);
                float e2 = __expf(acc[mi][ni][2] * 1.25f);
                float e3 = __expf(acc[mi][ni][3] * 1.25f);
                acc[mi][ni][0] = e0; acc[mi][ni][1] = e1;
                acc[mi][ni][2] = e2; acc[mi][ni][3] = e3;
                float2 p0 = *(const float2*)&pos[(size_t)r0 * N + c];
                float2 p1 = *(const float2*)&pos[(size_t)r1 * N + c];
                rp[mi][0] += e0 + e1;            rp[mi][1] += e2 + e3;
                rpm[mi][0] += e0 * p0.x + e1 * p0.y;
                rpm[mi][1] += e2 * p1.x + e3 * p1.y;
            }
        }
        #pragma unroll
        for (int mi = 0; mi < 4; mi++) {
            int r = wm + mi * 16 + g;
            atomicAdd(&srow[r], rp[mi][0]);
            atomicAdd(&srow[r + 8], rp[mi][1]);
            atomicAdd(&srowm[r], rpm[mi][0]);
            atomicAdd(&srowm[r + 8], rpm[mi][1]);
        }
        // transpose e-tile into smem: et[col_local][row_local], pitch 65
        float* et = (float*)dsm + warp * (32 * 65);
        #pragma unroll
        for (int mi = 0; mi < 4; mi++)
            #pragma unroll
            for (int ni = 0; ni < 4; ni++)
                #pragma unroll
                for (int q = 0; q < 4; q++) {
                    int rl = mi * 16 + g + ((q >= 2) ? 8 : 0);
                    int cl = ni * 8 + t4 * 2 + (q & 1);
                    et[cl * 65 + rl] = acc[mi][ni][q];
                }
        __syncwarp();
        // lane owns one column; pos column read is contiguous
        int c = n0 + wn + lane;
        const float4* pc = (const float4*)&pos[(size_t)c * N + m0 + wm];
        float cs = 0.f, csm = 0.f;
        #pragma unroll
        for (int q = 0; q < 16; q++) {
            float4 m4 = pc[q];
            float a0 = et[lane * 65 + q * 4 + 0];
            float a1 = et[lane * 65 + q * 4 + 1];
            float a2 = et[lane * 65 + q * 4 + 2];
            float a3 = et[lane * 65 + q * 4 + 3];
            cs  += a0 + a1 + a2 + a3;
            csm += a0 * m4.x + a1 * m4.y + a2 * m4.z + a3 * m4.w;
        }
        atomicAdd(&colsum[c], cs);
        atomicAdd(&mcol[c], csm);
        __syncthreads();
        if (tid < 128) {
            atomicAdd(&rowsum[m0 + tid], srow[tid]);
            atomicAdd(&mrow[m0 + tid], srowm[tid]);
        }
    } else {
        #pragma unroll
        for (int mi = 0; mi < 4; mi++) {
            int r0 = m0 + wm + mi * 16 + g;
            #pragma unroll
            for (int ni = 0; ni < 4; ni++) {
                int c = n0 + wn + ni * 8 + t4 * 2;
                float2 bc = *(const float2*)&bias[c];
                float v0 = acc[mi][ni][0] + bc.x;
                float v1 = acc[mi][ni][1] + bc.y;
                float v2 = acc[mi][ni][2] + bc.x;
                float v3 = acc[mi][ni][3] + bc.y;
                if (MODE == 0) {
                    v0 = (v0 > 0.f) ? v0 : expm1f(v0);
                    v1 = (v1 > 0.f) ? v1 : expm1f(v1);
                    v2 = (v2 > 0.f) ? v2 : expm1f(v2);
                    v3 = (v3 > 0.f) ? v3 : expm1f(v3);
                }
                *(uint32_t*)&C[(size_t)r0 * Nc + c] = bf2_pack(v0, v1);
                *(uint32_t*)&C[(size_t)(r0 + 8) * Nc + c] = bf2_pack(v2, v3);
            }
        }
    }
}

// ---------------- small utility kernels ------------------------------------
__global__ void zero_scalars_k(double* s) {
    if (threadIdx.x < 4) s[threadIdx.x] = 0.0;
}

__global__ void zero4_k(float* a, float* b, float* c, float* d) {
    int i = blockIdx.x * blockDim.x + threadIdx.x;
    if (i < N) { a[i] = 0.f; b[i] = 0.f; c[i] = 0.f; d[i] = 0.f; }
}

__global__ void conv_bf16_k(const float* __restrict__ src, __nv_bfloat16* __restrict__ dst, int n) {
    int idx = (blockIdx.x * blockDim.x + threadIdx.x) * 4;
    if (idx < n) {
        float4 v = *(const float4*)&src[idx];
        *(__nv_bfloat162*)&dst[idx] = __floats2bfloat162_rn(v.x, v.y);
        *(__nv_bfloat162*)&dst[idx + 2] = __floats2bfloat162_rn(v.z, v.w);
    }
}

// convert 4 inputs to bf16 (stacked) AND emit combined bf16 z1/z2 in one pass
__global__ void conv4_combine_k(const float* __restrict__ a, const float* __restrict__ b,
                                const float* __restrict__ c, const float* __restrict__ d,
                                const float* __restrict__ gamma,
                                __nv_bfloat16* __restrict__ dst,
                                __nv_bfloat16* __restrict__ z1, __nv_bfloat16* __restrict__ z2) {
    float gm = *gamma;
    int idx = (blockIdx.x * blockDim.x + threadIdx.x) * 4;
    if (idx < N * D) {
        float4 v0 = *(const float4*)&a[idx];
        float4 v1 = *(const float4*)&b[idx];
        float4 v2 = *(const float4*)&c[idx];
        float4 v3 = *(const float4*)&d[idx];
        __nv_bfloat16* o0 = dst + idx;
        __nv_bfloat16* o1 = dst + (size_t)N * D + idx;
        __nv_bfloat16* o2 = dst + (size_t)2 * N * D + idx;
        __nv_bfloat16* o3 = dst + (size_t)3 * N * D + idx;
        *(__nv_bfloat162*)&o0[0] = __floats2bfloat162_rn(v0.x, v0.y);
        *(__nv_bfloat162*)&o0[2] = __floats2bfloat162_rn(v0.z, v0.w);
        *(__nv_bfloat162*)&o1[0] = __floats2bfloat162_rn(v1.x, v1.y);
        *(__nv_bfloat162*)&o1[2] = __floats2bfloat162_rn(v1.z, v1.w);
        *(__nv_bfloat162*)&o2[0] = __floats2bfloat162_rn(v2.x, v2.y);
        *(__nv_bfloat162*)&o2[2] = __floats2bfloat162_rn(v2.z, v2.w);
        *(__nv_bfloat162*)&o3[0] = __floats2bfloat162_rn(v3.x, v3.y);
        *(__nv_bfloat162*)&o3[2] = __floats2bfloat162_rn(v3.z, v3.w);
        float og = 1.f - gm;
        *(__nv_bfloat162*)&z1[idx]     = __floats2bfloat162_rn(og*v0.x + gm*v1.x, og*v0.y + gm*v1.y);
        *(__nv_bfloat162*)&z1[idx + 2] = __floats2bfloat162_rn(og*v0.z + gm*v1.z, og*v0.w + gm*v1.w);
        *(__nv_bfloat162*)&z2[idx]     = __floats2bfloat162_rn(og*v2.x + gm*v3.x, og*v2.y + gm*v3.y);
        *(__nv_bfloat162*)&z2[idx + 2] = __floats2bfloat162_rn(og*v2.z + gm*v3.z, og*v2.w + gm*v3.w);
    }
}

// normalize rows in place (bf16), one warp per row, 4N rows
__global__ void normalize16_k(__nv_bfloat16* __restrict__ P) {
    int row = (blockIdx.x * blockDim.x + threadIdx.x) >> 5;
    int lane = threadIdx.x & 31;
    if (row >= 4 * N) return;
    __nv_bfloat162* p = (__nv_bfloat162*)(P + (size_t)row * D);
    float ss = 0.f;
    float2 v[16];
    #pragma unroll
    for (int u = 0; u < 16; u++) {
        v[u] = __bfloat1622float2(p[lane + u * 32]);
        ss += v[u].x * v[u].x + v[u].y * v[u].y;
    }
    #pragma unroll
    for (int o = 16; o; o >>= 1) ss += __shfl_xor_sync(0xffffffffu, ss, o);
    float inv = rsqrtf(ss);
    #pragma unroll
    for (int u = 0; u < 16; u++)
        p[lane + u * 32] = __floats2bfloat162_rn(v[u].x * inv, v[u].y * inv);
}

// ---------------- lori reduction --------------------------------------------
__global__ void lori_reduce_k(const float* __restrict__ mrow, const float* __restrict__ rowsum,
                              const float* __restrict__ mcol, const float* __restrict__ colsum,
                              double* __restrict__ target) {
    __shared__ float sm[8];
    int i = blockIdx.x * blockDim.x + threadIdx.x;
    float v = 0.f;
    if (i < N)
        v = logf(mrow[i]) - logf(rowsum[i] + 1e-8f)
          + logf(mcol[i]) - logf(colsum[i] + 1e-8f);
    #pragma unroll
    for (int o = 16; o; o >>= 1) v += __shfl_xor_sync(0xffffffffu, v, o);
    int lane = threadIdx.x & 31, w = threadIdx.x >> 5;
    if (lane == 0) sm[w] = v;
    __syncthreads();
    if (threadIdx.x < 8) {
        float t = sm[threadIdx.x];
        #pragma unroll
        for (int o = 4; o; o >>= 1) t += __shfl_xor_sync(0xffu, t, o);
        if (threadIdx.x == 0) atomicAdd(target, (double)t);
    }
}

// ---------------- InfoNCE LSE over 100 pseudo-random negatives -------------
__global__ __launch_bounds__(128)
void neg_lse_k(const __nv_bfloat16* __restrict__ z1, const __nv_bfloat16* __restrict__ z2,
               const float* __restrict__ md, float* __restrict__ lse) {
    __shared__ float2 zrow[D / 2];
    __shared__ int idxs[NUM_NEG + 32];
    __shared__ float vals[NUM_NEG];
    int i = blockIdx.x;
    const __nv_bfloat162* zi = (const __nv_bfloat162*)(z1 + (size_t)i * D);
    for (int d = threadIdx.x; d < D / 2; d += blockDim.x)
        zrow[d] = __bfloat1622float2(zi[d]);
    int warp = threadIdx.x >> 5, lane = threadIdx.x & 31;
    if (warp == 0) {
        // warp-parallel selection of first NUM_NEG unmasked candidates (t-order)
        const float* mr = md + (size_t)i * N;
        unsigned start = ((unsigned)i * 2654435761u) & (N - 1);
        int cnt = 0;
        unsigned t = 0;
        while (cnt < NUM_NEG) {
            int c = (int)((start + (t + lane) * 97u) & (N - 1));
            float mv = mr[c];
            unsigned bal = __ballot_sync(0xffffffffu, mv == 0.f);
            int prefix = __popc(bal & ((1u << lane) - 1));
            if (mv == 0.f && cnt + prefix < NUM_NEG + 32) idxs[cnt + prefix] = c;
            cnt += __popc(bal);
            t += 32;
        }
    }
    __syncthreads();
    for (int k = warp; k < NUM_NEG; k += 4) {
        const __nv_bfloat162* zc = (const __nv_bfloat162*)(z2 + (size_t)idxs[k] * D);
        float s = 0.f;
        #pragma unroll 4
        for (int d = lane; d < D / 2; d += 32) {
            float2 x = zrow[d];
            float2 y = __bfloat1622float2(zc[d]);
            s = fmaf(x.x, y.x, s);
            s = fmaf(x.y, y.y, s);
        }
        #pragma unroll
        for (int o = 16; o; o >>= 1) s += __shfl_xor_sync(0xffffffffu, s, o);
        if (lane == 0) vals[k] = s;
    }
    __syncthreads();
    if (threadIdx.x == 0) {
        float m = -1e30f;
        for (int k = 0; k < NUM_NEG; k++) m = fmaxf(m, vals[k]);
        float ss = 0.f;
        for (int k = 0; k < NUM_NEG; k++) ss += __expf((vals[k] - m) * 10.0f);
        lse[i] = m * 10.0f + logf(ss);   // 1/INFONCE_TAU = 10
    }
}

// ---------------- InfoNCE positive pairs (warp per row) --------------------
__global__ void inf_pairs_k(const __nv_bfloat16* __restrict__ z1, const __nv_bfloat16* __restrict__ z2,
                            const float* __restrict__ md, const float* __restrict__ lse,
                            double* __restrict__ s) {
    int warp = (blockIdx.x * blockDim.x + threadIdx.x) >> 5;
    int lane = threadIdx.x & 31;
    if (warp >= N) return;
    int i = warp;
    const float* mr = md + (size_t)i * N;
    const __nv_bfloat162* Zi = (const __nv_bfloat162*)(z1 + (size_t)i * D);
    float2 zi[16];
    #pragma unroll
    for (int u = 0; u < 16; u++) zi[u] = __bfloat1622float2(Zi[lane + u * 32]);
    float L = lse[i];
    float sum = 0.f;
    int cnt = 0;
    for (int jb = 0; jb < N; jb += 32) {
        float pv = mr[jb + lane];
        unsigned mask = __ballot_sync(0xffffffffu, pv > 0.f);
        while (mask) {
            int b = __ffs(mask) - 1;
            mask &= mask - 1;
            int j = jb + b;
            const __nv_bfloat162* Zj = (const __nv_bfloat162*)(z2 + (size_t)j * D);
            float dot = 0.f;
            #pragma unroll
            for (int u = 0; u < 16; u++) {
                float2 y = __bfloat1622float2(Zj[lane + u * 32]);
                dot = fmaf(zi[u].x, y.x, dot);
                dot = fmaf(zi[u].y, y.y, dot);
            }
            #pragma unroll
            for (int o = 16; o; o >>= 1) dot += __shfl_xor_sync(0xffffffffu, dot, o);
            float p = dot * 10.0f;
            float mx = fmaxf(p, L);
            float pp = mx + logf(__expf(p - mx) + __expf(L - mx)) - p;
            sum += pp;
            cnt++;
        }
    }
    if (lane == 0) {
        atomicAdd(&s[2], (double)sum);
        atomicAdd(&s[3], (double)cnt);
    }
}

// ---------------- finalize --------------------------------------------------
__global__ void finalize_k(float* out, const double* s) {
    double gcl = -0.5 * (s[0] + s[1]) / (double)N;
    out[0] = (float)(gcl + s[2] / s[3]);
}

// ---------------- launcher --------------------------------------------------
extern "C" void kernel_launch(void* const* d_in, const int* in_sizes, int n_in,
                              void* d_out, int out_size) {
    const float* z_mp1 = (const float*)d_in[0];
    const float* z_sc1 = (const float*)d_in[1];
    const float* pos1  = (const float*)d_in[2];
    const float* z_mp2 = (const float*)d_in[3];
    const float* z_sc2 = (const float*)d_in[4];
    const float* pos2  = (const float*)d_in[5];
    const float* md    = (const float*)d_in[6];
    const float* gamma = (const float*)d_in[7];
    const float* W1 = (const float*)d_in[8];
    const float* b1 = (const float*)d_in[9];
    const float* W2 = (const float*)d_in[10];
    const float* b2 = (const float*)d_in[11];
    float* out = (float*)d_out;

    __nv_bfloat16 *gZ, *gH, *gP, *gW1, *gW2, *gz1, *gz2;
    float *grow, *gcol, *gmr, *gmc, *glse;
    double* gs;
    cudaGetSymbolAddress((void**)&gZ, g_Zall);
    cudaGetSymbolAddress((void**)&gH, g_Hall);
    cudaGetSymbolAddress((void**)&gP, g_Pall);
    cudaGetSymbolAddress((void**)&gW1, g_W1bf);
    cudaGetSymbolAddress((void**)&gW2, g_W2bf);
    cudaGetSymbolAddress((void**)&gz1, g_z1);
    cudaGetSymbolAddress((void**)&gz2, g_z2);
    cudaGetSymbolAddress((void**)&grow, g_rowsum);
    cudaGetSymbolAddress((void**)&gcol, g_colsum);
    cudaGetSymbolAddress((void**)&gmr, g_mrow);
    cudaGetSymbolAddress((void**)&gmc, g_mcol);
    cudaGetSymbolAddress((void**)&glse, g_lse);
    cudaGetSymbolAddress((void**)&gs, g_s);

    cudaFuncSetAttribute(mm_bf16_k<0>, cudaFuncAttributeMaxDynamicSharedMemorySize, DSMEM);
    cudaFuncSetAttribute(mm_bf16_k<1>, cudaFuncAttributeMaxDynamicSharedMemorySize, DSMEM);
    cudaFuncSetAttribute(mm_bf16_k<2>, cudaFuncAttributeMaxDynamicSharedMemorySize, DSMEM);

    zero_scalars_k<<<1, 32>>>(gs);
    conv_bf16_k<<<(D * D / 4 + 255) / 256, 256>>>(W1, gW1, D * D);
    conv_bf16_k<<<(D * D / 4 + 255) / 256, 256>>>(W2, gW2, D * D);
    conv4_combine_k<<<(N * D / 4 + 255) / 256, 256>>>(z_mp1, z_sc1, z_mp2, z_sc2, gamma, gZ, gz1, gz2);

    // batched projection MLP: layer1 (ELU) then layer2, M = 16384
    dim3 gproj(D / 128, 4 * N / 128);      // (8, 128)
    mm_bf16_k<0><<<gproj, 256, DSMEM>>>(gZ, gW1, b1, gH, nullptr, nullptr, nullptr, nullptr, nullptr, D);
    mm_bf16_k<1><<<gproj, 256, DSMEM>>>(gH, gW2, b2, gP, nullptr, nullptr, nullptr, nullptr, nullptr, D);
    normalize16_k<<<4 * N / 8, 256>>>(gP);

    dim3 gsim(N / 128, N / 128);           // (32, 32)
    const float* poss[2] = {pos1, pos2};
    for (int r = 0; r < 2; r++) {
        zero4_k<<<N / 256, 256>>>(grow, gcol, gmr, gmc);
        mm_bf16_k<2><<<gsim, 256, DSMEM>>>(gP + (size_t)(2 * r) * N * D,
                                           gP + (size_t)(2 * r + 1) * N * D,
                                           nullptr, nullptr, poss[r],
                                           grow, gcol, gmr, gmc, N);
        lori_reduce_k<<<N / 256, 256>>>(gmr, grow, gmc, gcol, &gs[r]);
    }

    neg_lse_k<<<N, 128>>>(gz1, gz2, md, glse);
    inf_pairs_k<<<N / 8, 256>>>(gz1, gz2, md, glse, gs);
    finalize_k<<<1, 1>>>(out, gs);
}

// round 13
// speedup vs baseline: 1.7565x; 1.0157x over previous
#include <cuda_runtime.h>
#include <cuda_bf16.h>
#include <cstdint>
#include <math.h>

#define N 4096
#define D 1024
#define NUM_NEG 100
#define NT 16            // K=1024 / 64
#define STAGE_BYTES 32768
#define DSMEM 98304      // 3 stages x 32KB (epilogue et overlaps)

// ---------------- scratch (device globals; no allocation allowed) ----------
__device__ __nv_bfloat16 g_Zall[4 * N * D];
__device__ __nv_bfloat16 g_Hall[4 * N * D];
__device__ __nv_bfloat16 g_Pall[4 * N * D];
__device__ __nv_bfloat16 g_W1bf[D * D];
__device__ __nv_bfloat16 g_W2bf[D * D];
__device__ __nv_bfloat16 g_z1[N * D];
__device__ __nv_bfloat16 g_z2[N * D];
__device__ float g_rowsum[2 * N], g_colsum[2 * N], g_mrow[2 * N], g_mcol[2 * N], g_lse[N];
__device__ double g_s[4];  // [0]=gcl1 logsum, [1]=gcl2 logsum, [2]=pair_sum, [3]=pair_cnt

// ---------------- helpers ---------------------------------------------------
__device__ __forceinline__ uint32_t bf2_pack(float a, float b) {
    __nv_bfloat162 t = __floats2bfloat162_rn(a, b);
    return *reinterpret_cast<uint32_t*>(&t);
}

__device__ __forceinline__ void mma16816(float* c, const uint32_t* a, const uint32_t* b) {
    asm volatile(
        "mma.sync.aligned.m16n8k16.row.col.f32.bf16.bf16.f32 "
        "{%0,%1,%2,%3}, {%4,%5,%6,%7}, {%8,%9}, {%0,%1,%2,%3};"
        : "+f"(c[0]), "+f"(c[1]), "+f"(c[2]), "+f"(c[3])
        : "r"(a[0]), "r"(a[1]), "r"(a[2]), "r"(a[3]), "r"(b[0]), "r"(b[1]));
}

__device__ __forceinline__ void ldsm4(uint32_t* r, uint32_t saddr) {
    asm volatile("ldmatrix.sync.aligned.m8n8.x4.shared.b16 {%0,%1,%2,%3}, [%4];"
                 : "=r"(r[0]), "=r"(r[1]), "=r"(r[2]), "=r"(r[3]) : "r"(saddr));
}

template <int W>
__device__ __forceinline__ void cpwait() {
    asm volatile("cp.async.wait_group %0;" :: "n"(W));
}

// swizzled byte offset inside a 128x64 bf16 stage tile (rows of 128B, 16B chunks)
__device__ __forceinline__ uint32_t SWZ64(int r, int ch) {
    return (uint32_t)(r * 128 + ((ch ^ (r & 7)) << 4));
}

// load one 64-K stage of A(128 rows) + B(128 rows), 256 threads
__device__ __forceinline__ void ld_stage(
    const __nv_bfloat16* __restrict__ A, const __nv_bfloat16* __restrict__ B,
    int m0, int n0, int kt, uint32_t st, int tid) {
    #pragma unroll
    for (int i = 0; i < 4; i++) {
        int idx = tid + i * 256;
        int row = idx >> 3, ch = idx & 7;
        const __nv_bfloat16* g = &A[(size_t)(m0 + row) * D + kt + ch * 8];
        asm volatile("cp.async.cg.shared.global [%0], [%1], 16;"
                     :: "r"(st + SWZ64(row, ch)), "l"(g));
    }
    #pragma unroll
    for (int i = 0; i < 4; i++) {
        int idx = tid + i * 256;
        int row = idx >> 3, ch = idx & 7;
        const __nv_bfloat16* g = &B[(size_t)(n0 + row) * D + kt + ch * 8];
        asm volatile("cp.async.cg.shared.global [%0], [%1], 16;"
                     :: "r"(st + 16384 + SWZ64(row, ch)), "l"(g));
    }
}

// ---------------- bf16 HMMA NT GEMM ----------------------------------------
// C[i,j] = sum_k A[i,k]*B[j,k].  MODE 0: +bias+ELU->bf16, 1: +bias->bf16,
// 2: sim epilogue over blockIdx.z-selected pass (both sim passes one grid)
template <int MODE>
__global__ __launch_bounds__(256, 2)
void mm_bf16_k(const __nv_bfloat16* __restrict__ Abase, const __nv_bfloat16* __restrict__ Bbase,
               const float* __restrict__ bias, __nv_bfloat16* __restrict__ C,
               const float* __restrict__ pos1, const float* __restrict__ pos2,
               float* __restrict__ rowsum, float* __restrict__ colsum,
               float* __restrict__ mrow, float* __restrict__ mcol, int Nc) {
    extern __shared__ __align__(16) char dsm[];
    __shared__ float srow[128], srowm[128];

    int tid = threadIdx.x;
    int warp = tid >> 5, lane = tid & 31;
    int g = lane >> 2, t4 = lane & 3;
    int wm = (warp >> 2) * 64;   // 2 warp-rows x 64
    int wn = (warp & 3) * 32;    // 4 warp-cols x 32
    int m0 = blockIdx.y * 128, n0 = blockIdx.x * 128;
    int zr = blockIdx.z;
    const __nv_bfloat16* A = Abase;
    const __nv_bfloat16* B = Bbase;
    const float* pos = pos1;
    if (MODE == 2) {
        A = Abase + (size_t)(2 * zr) * N * D;
        B = Abase + (size_t)(2 * zr + 1) * N * D;
        pos = (zr == 0) ? pos1 : pos2;
    }
    uint32_t sb = (uint32_t)__cvta_generic_to_shared(dsm);

    float acc[4][4][4] = {};

    ld_stage(A, B, m0, n0, 0, sb, tid);
    asm volatile("cp.async.commit_group;");
    ld_stage(A, B, m0, n0, 64, sb + STAGE_BYTES, tid);
    asm volatile("cp.async.commit_group;");

    int lr = lane & 15, lc = lane >> 4;
    for (int s = 0; s < NT; s++) {
        if (s < NT - 1) cpwait<1>(); else cpwait<0>();
        __syncthreads();
        if (s + 2 < NT) {
            ld_stage(A, B, m0, n0, (s + 2) * 64, sb + ((s + 2) % 3) * STAGE_BYTES, tid);
            asm volatile("cp.async.commit_group;");
        }
        uint32_t ab = sb + (s % 3) * STAGE_BYTES;
        uint32_t bb = ab + 16384;
        #pragma unroll
        for (int ks = 0; ks < 4; ks++) {
            int ch = ks * 2 + lc;
            uint32_t a[4][4], b[2][4];
            #pragma unroll
            for (int mi = 0; mi < 4; mi++)
                ldsm4(a[mi], ab + SWZ64(wm + mi * 16 + lr, ch));
            #pragma unroll
            for (int nb = 0; nb < 2; nb++)
                ldsm4(b[nb], bb + SWZ64(wn + nb * 16 + lr, ch));
            #pragma unroll
            for (int mi = 0; mi < 4; mi++)
                #pragma unroll
                for (int ni = 0; ni < 4; ni++) {
                    uint32_t bf[2] = { b[ni >> 1][ni & 1], b[ni >> 1][(ni & 1) + 2] };
                    mma16816(acc[mi][ni], a[mi], bf);
                }
        }
    }
    __syncthreads();   // smem reuse barrier (MODE 2 epilogue overlays stage bufs)

    if (MODE == 2) {
        if (tid < 128) { srow[tid] = 0.f; srowm[tid] = 0.f; }
        __syncthreads();
        float rp[4][2] = {}, rpm[4][2] = {};
        #pragma unroll
        for (int mi = 0; mi < 4; mi++) {
            int r0 = m0 + wm + mi * 16 + g;
            int r1 = r0 + 8;
            #pragma unroll
            for (int ni = 0; ni < 4; ni++) {
                int c = n0 + wn + ni * 8 + t4 * 2;
                float e0 = __expf(acc[mi][ni][0] * 1.25f);   // 1/TAU
                float e1 = __expf(acc[mi][ni][1] * 1.25f);
                float e2 = __expf(acc[mi][ni][2] * 1.25f);
                float e3 = __expf(acc[mi][ni][3] * 1.25f);
                acc[mi][ni][0] = e0; acc[mi][ni][1] = e1;
                acc[mi][ni][2] = e2; acc[mi][ni][3] = e3;
                float2 p0 = *(const float2*)&pos[(size_t)r0 * N + c];
                float2 p1 = *(const float2*)&pos[(size_t)r1 * N + c];
                rp[mi][0] += e0 + e1;            rp[mi][1] += e2 + e3;
                rpm[mi][0] += e0 * p0.x + e1 * p0.y;
                rpm[mi][1] += e2 * p1.x + e3 * p1.y;
            }
        }
        #pragma unroll
        for (int mi = 0; mi < 4; mi++) {
            int r = wm + mi * 16 + g;
            atomicAdd(&srow[r], rp[mi][0]);
            atomicAdd(&srow[r + 8], rp[mi][1]);
            atomicAdd(&srowm[r], rpm[mi][0]);
            atomicAdd(&srowm[r + 8], rpm[mi][1]);
        }
        // transpose e-tile into smem: et[col_local][row_local], pitch 65
        float* et = (float*)dsm + warp * (32 * 65);
        #pragma unroll
        for (int mi = 0; mi < 4; mi++)
            #pragma unroll
            for (int ni = 0; ni < 4; ni++)
                #pragma unroll
                for (int q = 0; q < 4; q++) {
                    int rl = mi * 16 + g + ((q >= 2) ? 8 : 0);
                    int cl = ni * 8 + t4 * 2 + (q & 1);
                    et[cl * 65 + rl] = acc[mi][ni][q];
                }
        __syncwarp();
        // lane owns one column; pos column read is contiguous
        int c = n0 + wn + lane;
        const float4* pc = (const float4*)&pos[(size_t)c * N + m0 + wm];
        float cs = 0.f, csm = 0.f;
        #pragma unroll
        for (int q = 0; q < 16; q++) {
            float4 m4 = pc[q];
            float a0 = et[lane * 65 + q * 4 + 0];
            float a1 = et[lane * 65 + q * 4 + 1];
            float a2 = et[lane * 65 + q * 4 + 2];
            float a3 = et[lane * 65 + q * 4 + 3];
            cs  += a0 + a1 + a2 + a3;
            csm += a0 * m4.x + a1 * m4.y + a2 * m4.z + a3 * m4.w;
        }
        atomicAdd(&colsum[zr * N + c], cs);
        atomicAdd(&mcol[zr * N + c], csm);
        __syncthreads();
        if (tid < 128) {
            atomicAdd(&rowsum[zr * N + m0 + tid], srow[tid]);
            atomicAdd(&mrow[zr * N + m0 + tid], srowm[tid]);
        }
    } else {
        #pragma unroll
        for (int mi = 0; mi < 4; mi++) {
            int r0 = m0 + wm + mi * 16 + g;
            #pragma unroll
            for (int ni = 0; ni < 4; ni++) {
                int c = n0 + wn + ni * 8 + t4 * 2;
                float2 bc = *(const float2*)&bias[c];
                float v0 = acc[mi][ni][0] + bc.x;
                float v1 = acc[mi][ni][1] + bc.y;
                float v2 = acc[mi][ni][2] + bc.x;
                float v3 = acc[mi][ni][3] + bc.y;
                if (MODE == 0) {
                    v0 = (v0 > 0.f) ? v0 : expm1f(v0);
                    v1 = (v1 > 0.f) ? v1 : expm1f(v1);
                    v2 = (v2 > 0.f) ? v2 : expm1f(v2);
                    v3 = (v3 > 0.f) ? v3 : expm1f(v3);
                }
                *(uint32_t*)&C[(size_t)r0 * Nc + c] = bf2_pack(v0, v1);
                *(uint32_t*)&C[(size_t)(r0 + 8) * Nc + c] = bf2_pack(v2, v3);
            }
        }
    }
}

// ---------------- small utility kernels ------------------------------------
__global__ void zero_all_k(double* s, float* a, float* b, float* c, float* d) {
    int i = blockIdx.x * blockDim.x + threadIdx.x;
    if (i < 4) s[i] = 0.0;
    if (i < 2 * N) { a[i] = 0.f; b[i] = 0.f; c[i] = 0.f; d[i] = 0.f; }
}

__global__ void conv_bf16_k(const float* __restrict__ src, __nv_bfloat16* __restrict__ dst, int n) {
    int idx = (blockIdx.x * blockDim.x + threadIdx.x) * 4;
    if (idx < n) {
        float4 v = *(const float4*)&src[idx];
        *(__nv_bfloat162*)&dst[idx] = __floats2bfloat162_rn(v.x, v.y);
        *(__nv_bfloat162*)&dst[idx + 2] = __floats2bfloat162_rn(v.z, v.w);
    }
}

// convert 4 inputs to bf16 (stacked) AND emit combined bf16 z1/z2 in one pass
__global__ void conv4_combine_k(const float* __restrict__ a, const float* __restrict__ b,
                                const float* __restrict__ c, const float* __restrict__ d,
                                const float* __restrict__ gamma,
                                __nv_bfloat16* __restrict__ dst,
                                __nv_bfloat16* __restrict__ z1, __nv_bfloat16* __restrict__ z2) {
    float gm = *gamma;
    int idx = (blockIdx.x * blockDim.x + threadIdx.x) * 4;
    if (idx < N * D) {
        float4 v0 = *(const float4*)&a[idx];
        float4 v1 = *(const float4*)&b[idx];
        float4 v2 = *(const float4*)&c[idx];
        float4 v3 = *(const float4*)&d[idx];
        __nv_bfloat16* o0 = dst + idx;
        __nv_bfloat16* o1 = dst + (size_t)N * D + idx;
        __nv_bfloat16* o2 = dst + (size_t)2 * N * D + idx;
        __nv_bfloat16* o3 = dst + (size_t)3 * N * D + idx;
        *(__nv_bfloat162*)&o0[0] = __floats2bfloat162_rn(v0.x, v0.y);
        *(__nv_bfloat162*)&o0[2] = __floats2bfloat162_rn(v0.z, v0.w);
        *(__nv_bfloat162*)&o1[0] = __floats2bfloat162_rn(v1.x, v1.y);
        *(__nv_bfloat162*)&o1[2] = __floats2bfloat162_rn(v1.z, v1.w);
        *(__nv_bfloat162*)&o2[0] = __floats2bfloat162_rn(v2.x, v2.y);
        *(__nv_bfloat162*)&o2[2] = __floats2bfloat162_rn(v2.z, v2.w);
        *(__nv_bfloat162*)&o3[0] = __floats2bfloat162_rn(v3.x, v3.y);
        *(__nv_bfloat162*)&o3[2] = __floats2bfloat162_rn(v3.z, v3.w);
        float og = 1.f - gm;
        *(__nv_bfloat162*)&z1[idx]     = __floats2bfloat162_rn(og*v0.x + gm*v1.x, og*v0.y + gm*v1.y);
        *(__nv_bfloat162*)&z1[idx + 2] = __floats2bfloat162_rn(og*v0.z + gm*v1.z, og*v0.w + gm*v1.w);
        *(__nv_bfloat162*)&z2[idx]     = __floats2bfloat162_rn(og*v2.x + gm*v3.x, og*v2.y + gm*v3.y);
        *(__nv_bfloat162*)&z2[idx + 2] = __floats2bfloat162_rn(og*v2.z + gm*v3.z, og*v2.w + gm*v3.w);
    }
}

// normalize rows in place (bf16), one warp per row, 4N rows
__global__ void normalize16_k(__nv_bfloat16* __restrict__ P) {
    int row = (blockIdx.x * blockDim.x + threadIdx.x) >> 5;
    int lane = threadIdx.x & 31;
    if (row >= 4 * N) return;
    __nv_bfloat162* p = (__nv_bfloat162*)(P + (size_t)row * D);
    float ss = 0.f;
    float2 v[16];
    #pragma unroll
    for (int u = 0; u < 16; u++) {
        v[u] = __bfloat1622float2(p[lane + u * 32]);
        ss += v[u].x * v[u].x + v[u].y * v[u].y;
    }
    #pragma unroll
    for (int o = 16; o; o >>= 1) ss += __shfl_xor_sync(0xffffffffu, ss, o);
    float inv = rsqrtf(ss);
    #pragma unroll
    for (int u = 0; u < 16; u++)
        p[lane + u * 32] = __floats2bfloat162_rn(v[u].x * inv, v[u].y * inv);
}

// ---------------- lori reduction over both passes (2N entries) -------------
__global__ void lori_reduce_k(const float* __restrict__ mrow, const float* __restrict__ rowsum,
                              const float* __restrict__ mcol, const float* __restrict__ colsum,
                              double* __restrict__ s) {
    __shared__ float sm[8];
    int i = blockIdx.x * blockDim.x + threadIdx.x;   // 0 .. 2N-1, block spans one half only
    float v = 0.f;
    if (i < 2 * N)
        v = logf(mrow[i]) - logf(rowsum[i] + 1e-8f)
          + logf(mcol[i]) - logf(colsum[i] + 1e-8f);
    #pragma unroll
    for (int o = 16; o; o >>= 1) v += __shfl_xor_sync(0xffffffffu, v, o);
    int lane = threadIdx.x & 31, w = threadIdx.x >> 5;
    if (lane == 0) sm[w] = v;
    __syncthreads();
    if (threadIdx.x < 8) {
        float t = sm[threadIdx.x];
        #pragma unroll
        for (int o = 4; o; o >>= 1) t += __shfl_xor_sync(0xffu, t, o);
        if (threadIdx.x == 0)
            atomicAdd(&s[(blockIdx.x * blockDim.x) >= N ? 1 : 0], (double)t);
    }
}

// ---------------- InfoNCE LSE over 100 pseudo-random negatives -------------
__global__ __launch_bounds__(128)
void neg_lse_k(const __nv_bfloat16* __restrict__ z1, const __nv_bfloat16* __restrict__ z2,
               const float* __restrict__ md, float* __restrict__ lse) {
    __shared__ float2 zrow[D / 2];
    __shared__ int idxs[NUM_NEG + 32];
    __shared__ float vals[NUM_NEG];
    int i = blockIdx.x;
    const __nv_bfloat162* zi = (const __nv_bfloat162*)(z1 + (size_t)i * D);
    for (int d = threadIdx.x; d < D / 2; d += blockDim.x)
        zrow[d] = __bfloat1622float2(zi[d]);
    int warp = threadIdx.x >> 5, lane = threadIdx.x & 31;
    if (warp == 0) {
        // warp-parallel selection of first NUM_NEG unmasked candidates (t-order)
        const float* mr = md + (size_t)i * N;
        unsigned start = ((unsigned)i * 2654435761u) & (N - 1);
        int cnt = 0;
        unsigned t = 0;
        while (cnt < NUM_NEG) {
            int c = (int)((start + (t + lane) * 97u) & (N - 1));
            float mv = mr[c];
            unsigned bal = __ballot_sync(0xffffffffu, mv == 0.f);
            int prefix = __popc(bal & ((1u << lane) - 1));
            if (mv == 0.f && cnt + prefix < NUM_NEG + 32) idxs[cnt + prefix] = c;
            cnt += __popc(bal);
            t += 32;
        }
    }
    __syncthreads();
    for (int k = warp; k < NUM_NEG; k += 4) {
        const __nv_bfloat162* zc = (const __nv_bfloat162*)(z2 + (size_t)idxs[k] * D);
        float s = 0.f;
        #pragma unroll 4
        for (int d = lane; d < D / 2; d += 32) {
            float2 x = zrow[d];
            float2 y = __bfloat1622float2(zc[d]);
            s = fmaf(x.x, y.x, s);
            s = fmaf(x.y, y.y, s);
        }
        #pragma unroll
        for (int o = 16; o; o >>= 1) s += __shfl_xor_sync(0xffffffffu, s, o);
        if (lane == 0) vals[k] = s;
    }
    __syncthreads();
    if (threadIdx.x == 0) {
        float m = -1e30f;
        for (int k = 0; k < NUM_NEG; k++) m = fmaxf(m, vals[k]);
        float ss = 0.f;
        for (int k = 0; k < NUM_NEG; k++) ss += __expf((vals[k] - m) * 10.0f);
        lse[i] = m * 10.0f + logf(ss);   // 1/INFONCE_TAU = 10
    }
}

// ---------------- InfoNCE positive pairs (warp per row) --------------------
__global__ void inf_pairs_k(const __nv_bfloat16* __restrict__ z1, const __nv_bfloat16* __restrict__ z2,
                            const float* __restrict__ md, const float* __restrict__ lse,
                            double* __restrict__ s) {
    int warp = (blockIdx.x * blockDim.x + threadIdx.x) >> 5;
    int lane = threadIdx.x & 31;
    if (warp >= N) return;
    int i = warp;
    const float* mr = md + (size_t)i * N;
    const __nv_bfloat162* Zi = (const __nv_bfloat162*)(z1 + (size_t)i * D);
    float2 zi[16];
    #pragma unroll
    for (int u = 0; u < 16; u++) zi[u] = __bfloat1622float2(Zi[lane + u * 32]);
    float L = lse[i];
    float sum = 0.f;
    int cnt = 0;
    for (int jb = 0; jb < N; jb += 32) {
        float pv = mr[jb + lane];
        unsigned mask = __ballot_sync(0xffffffffu, pv > 0.f);
        while (mask) {
            int b = __ffs(mask) - 1;
            mask &= mask - 1;
            int j = jb + b;
            const __nv_bfloat162* Zj = (const __nv_bfloat162*)(z2 + (size_t)j * D);
            float dot = 0.f;
            #pragma unroll
            for (int u = 0; u < 16; u++) {
                float2 y = __bfloat1622float2(Zj[lane + u * 32]);
                dot = fmaf(zi[u].x, y.x, dot);
                dot = fmaf(zi[u].y, y.y, dot);
            }
            #pragma unroll
            for (int o = 16; o; o >>= 1) dot += __shfl_xor_sync(0xffffffffu, dot, o);
            float p = dot * 10.0f;
            float mx = fmaxf(p, L);
            float pp = mx + logf(__expf(p - mx) + __expf(L - mx)) - p;
            sum += pp;
            cnt++;
        }
    }
    if (lane == 0) {
        atomicAdd(&s[2], (double)sum);
        atomicAdd(&s[3], (double)cnt);
    }
}

// ---------------- finalize --------------------------------------------------
__global__ void finalize_k(float* out, const double* s) {
    double gcl = -0.5 * (s[0] + s[1]) / (double)N;
    out[0] = (float)(gcl + s[2] / s[3]);
}

// ---------------- launcher --------------------------------------------------
extern "C" void kernel_launch(void* const* d_in, const int* in_sizes, int n_in,
                              void* d_out, int out_size) {
    const float* z_mp1 = (const float*)d_in[0];
    const float* z_sc1 = (const float*)d_in[1];
    const float* pos1  = (const float*)d_in[2];
    const float* z_mp2 = (const float*)d_in[3];
    const float* z_sc2 = (const float*)d_in[4];
    const float* pos2  = (const float*)d_in[5];
    const float* md    = (const float*)d_in[6];
    const float* gamma = (const float*)d_in[7];
    const float* W1 = (const float*)d_in[8];
    const float* b1 = (const float*)d_in[9];
    const float* W2 = (const float*)d_in[10];
    const float* b2 = (const float*)d_in[11];
    float* out = (float*)d_out;

    __nv_bfloat16 *gZ, *gH, *gP, *gW1, *gW2, *gz1, *gz2;
    float *grow, *gcol, *gmr, *gmc, *glse;
    double* gs;
    cudaGetSymbolAddress((void**)&gZ, g_Zall);
    cudaGetSymbolAddress((void**)&gH, g_Hall);
    cudaGetSymbolAddress((void**)&gP, g_Pall);
    cudaGetSymbolAddress((void**)&gW1, g_W1bf);
    cudaGetSymbolAddress((void**)&gW2, g_W2bf);
    cudaGetSymbolAddress((void**)&gz1, g_z1);
    cudaGetSymbolAddress((void**)&gz2, g_z2);
    cudaGetSymbolAddress((void**)&grow, g_rowsum);
    cudaGetSymbolAddress((void**)&gcol, g_colsum);
    cudaGetSymbolAddress((void**)&gmr, g_mrow);
    cudaGetSymbolAddress((void**)&gmc, g_mcol);
    cudaGetSymbolAddress((void**)&glse, g_lse);
    cudaGetSymbolAddress((void**)&gs, g_s);

    cudaFuncSetAttribute(mm_bf16_k<0>, cudaFuncAttributeMaxDynamicSharedMemorySize, DSMEM);
    cudaFuncSetAttribute(mm_bf16_k<1>, cudaFuncAttributeMaxDynamicSharedMemorySize, DSMEM);
    cudaFuncSetAttribute(mm_bf16_k<2>, cudaFuncAttributeMaxDynamicSharedMemorySize, DSMEM);

    zero_all_k<<<(2 * N + 255) / 256, 256>>>(gs, grow, gcol, gmr, gmc);
    conv_bf16_k<<<(D * D / 4 + 255) / 256, 256>>>(W1, gW1, D * D);
    conv_bf16_k<<<(D * D / 4 + 255) / 256, 256>>>(W2, gW2, D * D);
    conv4_combine_k<<<(N * D / 4 + 255) / 256, 256>>>(z_mp1, z_sc1, z_mp2, z_sc2, gamma, gZ, gz1, gz2);

    // batched projection MLP: layer1 (ELU) then layer2, M = 16384
    dim3 gproj(D / 128, 4 * N / 128);      // (8, 128)
    mm_bf16_k<0><<<gproj, 256, DSMEM>>>(gZ, gW1, b1, gH, nullptr, nullptr, nullptr, nullptr, nullptr, nullptr, D);
    mm_bf16_k<1><<<gproj, 256, DSMEM>>>(gH, gW2, b2, gP, nullptr, nullptr, nullptr, nullptr, nullptr, nullptr, D);
    normalize16_k<<<4 * N / 8, 256>>>(gP);

    // both sim passes in one launch (z = pass index) — kills wave-quantization tail
    dim3 gsim(N / 128, N / 128, 2);        // (32, 32, 2)
    mm_bf16_k<2><<<gsim, 256, DSMEM>>>(gP, nullptr, nullptr, nullptr, pos1, pos2,
                                       grow, gcol, gmr, gmc, N);
    lori_reduce_k<<<2 * N / 256, 256>>>(gmr, grow, gmc, gcol, gs);

    neg_lse_k<<<N, 128>>>(gz1, gz2, md, glse);
    inf_pairs_k<<<N / 8, 256>>>(gz1, gz2, md, glse, gs);
    finalize_k<<<1, 1>>>(out, gs);
}

// round 14
// speedup vs baseline: 1.8994x; 1.0814x over previous
#include <cuda_runtime.h>
#include <cuda_bf16.h>
#include <cstdint>
#include <math.h>

#define N 4096
#define D 1024
#define NUM_NEG 100
#define NT 16            // K=1024 / 64
#define STAGE_BYTES 32768
#define DSMEM 98304      // 3 stages x 32KB (epilogue et overlaps)

// ---------------- scratch (device globals; no allocation allowed) ----------
__device__ __nv_bfloat16 g_Zall[4 * N * D];
__device__ __nv_bfloat16 g_Hall[4 * N * D];
__device__ __nv_bfloat16 g_Pall[4 * N * D];   // unnormalized projections
__device__ __nv_bfloat16 g_W1bf[D * D];
__device__ __nv_bfloat16 g_W2bf[D * D];
__device__ __nv_bfloat16 g_z1[N * D];
__device__ __nv_bfloat16 g_z2[N * D];
__device__ float g_norm2[4 * N];              // per-row sum of squares of P
__device__ float g_rowsum[2 * N], g_colsum[2 * N], g_mrow[2 * N], g_mcol[2 * N], g_lse[N];
__device__ double g_s[4];  // [0]=gcl1 logsum, [1]=gcl2 logsum, [2]=pair_sum, [3]=pair_cnt

// ---------------- helpers ---------------------------------------------------
__device__ __forceinline__ uint32_t bf2_pack(float a, float b) {
    __nv_bfloat162 t = __floats2bfloat162_rn(a, b);
    return *reinterpret_cast<uint32_t*>(&t);
}

__device__ __forceinline__ void mma16816(float* c, const uint32_t* a, const uint32_t* b) {
    asm volatile(
        "mma.sync.aligned.m16n8k16.row.col.f32.bf16.bf16.f32 "
        "{%0,%1,%2,%3}, {%4,%5,%6,%7}, {%8,%9}, {%0,%1,%2,%3};"
        : "+f"(c[0]), "+f"(c[1]), "+f"(c[2]), "+f"(c[3])
        : "r"(a[0]), "r"(a[1]), "r"(a[2]), "r"(a[3]), "r"(b[0]), "r"(b[1]));
}

__device__ __forceinline__ void ldsm4(uint32_t* r, uint32_t saddr) {
    asm volatile("ldmatrix.sync.aligned.m8n8.x4.shared.b16 {%0,%1,%2,%3}, [%4];"
                 : "=r"(r[0]), "=r"(r[1]), "=r"(r[2]), "=r"(r[3]) : "r"(saddr));
}

template <int W>
__device__ __forceinline__ void cpwait() {
    asm volatile("cp.async.wait_group %0;" :: "n"(W));
}

// swizzled byte offset inside a 128x64 bf16 stage tile (rows of 128B, 16B chunks)
__device__ __forceinline__ uint32_t SWZ64(int r, int ch) {
    return (uint32_t)(r * 128 + ((ch ^ (r & 7)) << 4));
}

// load one 64-K stage of A(128 rows) + B(128 rows), 256 threads
__device__ __forceinline__ void ld_stage(
    const __nv_bfloat16* __restrict__ A, const __nv_bfloat16* __restrict__ B,
    int m0, int n0, int kt, uint32_t st, int tid) {
    #pragma unroll
    for (int i = 0; i < 4; i++) {
        int idx = tid + i * 256;
        int row = idx >> 3, ch = idx & 7;
        const __nv_bfloat16* g = &A[(size_t)(m0 + row) * D + kt + ch * 8];
        asm volatile("cp.async.cg.shared.global [%0], [%1], 16;"
                     :: "r"(st + SWZ64(row, ch)), "l"(g));
    }
    #pragma unroll
    for (int i = 0; i < 4; i++) {
        int idx = tid + i * 256;
        int row = idx >> 3, ch = idx & 7;
        const __nv_bfloat16* g = &B[(size_t)(n0 + row) * D + kt + ch * 8];
        asm volatile("cp.async.cg.shared.global [%0], [%1], 16;"
                     :: "r"(st + 16384 + SWZ64(row, ch)), "l"(g));
    }
}

// ---------------- bf16 HMMA NT GEMM ----------------------------------------
// C[i,j] = sum_k A[i,k]*B[j,k].
// MODE 0: +bias+ELU->bf16
// MODE 1: +bias->bf16, accumulate per-row sum-of-squares into norms[]
// MODE 2: sim epilogue w/ inverse-norm rescale, blockIdx.z selects pass
template <int MODE>
__global__ __launch_bounds__(256, 2)
void mm_bf16_k(const __nv_bfloat16* __restrict__ Abase, const __nv_bfloat16* __restrict__ Bbase,
               const float* __restrict__ bias, __nv_bfloat16* __restrict__ C,
               const float* __restrict__ pos1, const float* __restrict__ pos2,
               float* __restrict__ norms,
               float* __restrict__ rowsum, float* __restrict__ colsum,
               float* __restrict__ mrow, float* __restrict__ mcol, int Nc) {
    extern __shared__ __align__(16) char dsm[];
    __shared__ float srow[128], srowm[128];
    __shared__ float sinvA[128], sinvB[128];

    int tid = threadIdx.x;
    int warp = tid >> 5, lane = tid & 31;
    int g = lane >> 2, t4 = lane & 3;
    int wm = (warp >> 2) * 64;   // 2 warp-rows x 64
    int wn = (warp & 3) * 32;    // 4 warp-cols x 32
    int m0 = blockIdx.y * 128, n0 = blockIdx.x * 128;
    int zr = blockIdx.z;
    const __nv_bfloat16* A = Abase;
    const __nv_bfloat16* B = Bbase;
    const float* pos = pos1;
    if (MODE == 2) {
        A = Abase + (size_t)(2 * zr) * N * D;
        B = Abase + (size_t)(2 * zr + 1) * N * D;
        pos = (zr == 0) ? pos1 : pos2;
    }
    uint32_t sb = (uint32_t)__cvta_generic_to_shared(dsm);

    float acc[4][4][4] = {};

    ld_stage(A, B, m0, n0, 0, sb, tid);
    asm volatile("cp.async.commit_group;");
    ld_stage(A, B, m0, n0, 64, sb + STAGE_BYTES, tid);
    asm volatile("cp.async.commit_group;");

    int lr = lane & 15, lc = lane >> 4;
    for (int s = 0; s < NT; s++) {
        if (s < NT - 1) cpwait<1>(); else cpwait<0>();
        __syncthreads();
        if (s + 2 < NT) {
            ld_stage(A, B, m0, n0, (s + 2) * 64, sb + ((s + 2) % 3) * STAGE_BYTES, tid);
            asm volatile("cp.async.commit_group;");
        }
        uint32_t ab = sb + (s % 3) * STAGE_BYTES;
        uint32_t bb = ab + 16384;
        #pragma unroll
        for (int ks = 0; ks < 4; ks++) {
            int ch = ks * 2 + lc;
            uint32_t a[4][4], b[2][4];
            #pragma unroll
            for (int mi = 0; mi < 4; mi++)
                ldsm4(a[mi], ab + SWZ64(wm + mi * 16 + lr, ch));
            #pragma unroll
            for (int nb = 0; nb < 2; nb++)
                ldsm4(b[nb], bb + SWZ64(wn + nb * 16 + lr, ch));
            #pragma unroll
            for (int mi = 0; mi < 4; mi++)
                #pragma unroll
                for (int ni = 0; ni < 4; ni++) {
                    uint32_t bf[2] = { b[ni >> 1][ni & 1], b[ni >> 1][(ni & 1) + 2] };
                    mma16816(acc[mi][ni], a[mi], bf);
                }
        }
    }
    __syncthreads();   // smem reuse barrier (MODE 2 epilogue overlays stage bufs)

    if (MODE == 2) {
        if (tid < 128) {
            srow[tid] = 0.f; srowm[tid] = 0.f;
            sinvA[tid] = rsqrtf(norms[(size_t)(2 * zr) * N + m0 + tid]);
            sinvB[tid] = rsqrtf(norms[(size_t)(2 * zr + 1) * N + n0 + tid]);
        }
        __syncthreads();
        float rp[4][2] = {}, rpm[4][2] = {};
        #pragma unroll
        for (int mi = 0; mi < 4; mi++) {
            int rl0 = wm + mi * 16 + g;
            int r0 = m0 + rl0;
            int r1 = r0 + 8;
            float ia0 = sinvA[rl0] * 1.25f;       // fold 1/TAU
            float ia1 = sinvA[rl0 + 8] * 1.25f;
            #pragma unroll
            for (int ni = 0; ni < 4; ni++) {
                int cl = wn + ni * 8 + t4 * 2;
                int c = n0 + cl;
                float ib0 = sinvB[cl], ib1 = sinvB[cl + 1];
                float e0 = __expf(acc[mi][ni][0] * ia0 * ib0);
                float e1 = __expf(acc[mi][ni][1] * ia0 * ib1);
                float e2 = __expf(acc[mi][ni][2] * ia1 * ib0);
                float e3 = __expf(acc[mi][ni][3] * ia1 * ib1);
                acc[mi][ni][0] = e0; acc[mi][ni][1] = e1;
                acc[mi][ni][2] = e2; acc[mi][ni][3] = e3;
                float2 p0 = *(const float2*)&pos[(size_t)r0 * N + c];
                float2 p1 = *(const float2*)&pos[(size_t)r1 * N + c];
                rp[mi][0] += e0 + e1;            rp[mi][1] += e2 + e3;
                rpm[mi][0] += e0 * p0.x + e1 * p0.y;
                rpm[mi][1] += e2 * p1.x + e3 * p1.y;
            }
        }
        #pragma unroll
        for (int mi = 0; mi < 4; mi++) {
            int r = wm + mi * 16 + g;
            atomicAdd(&srow[r], rp[mi][0]);
            atomicAdd(&srow[r + 8], rp[mi][1]);
            atomicAdd(&srowm[r], rpm[mi][0]);
            atomicAdd(&srowm[r + 8], rpm[mi][1]);
        }
        // transpose e-tile into smem: et[col_local][row_local], pitch 65
        float* et = (float*)dsm + warp * (32 * 65);
        #pragma unroll
        for (int mi = 0; mi < 4; mi++)
            #pragma unroll
            for (int ni = 0; ni < 4; ni++)
                #pragma unroll
                for (int q = 0; q < 4; q++) {
                    int rl = mi * 16 + g + ((q >= 2) ? 8 : 0);
                    int cl = ni * 8 + t4 * 2 + (q & 1);
                    et[cl * 65 + rl] = acc[mi][ni][q];
                }
        __syncwarp();
        // lane owns one column; pos column read is contiguous
        int c = n0 + wn + lane;
        const float4* pc = (const float4*)&pos[(size_t)c * N + m0 + wm];
        float cs = 0.f, csm = 0.f;
        #pragma unroll
        for (int q = 0; q < 16; q++) {
            float4 m4 = pc[q];
            float a0 = et[lane * 65 + q * 4 + 0];
            float a1 = et[lane * 65 + q * 4 + 1];
            float a2 = et[lane * 65 + q * 4 + 2];
            float a3 = et[lane * 65 + q * 4 + 3];
            cs  += a0 + a1 + a2 + a3;
            csm += a0 * m4.x + a1 * m4.y + a2 * m4.z + a3 * m4.w;
        }
        atomicAdd(&colsum[zr * N + c], cs);
        atomicAdd(&mcol[zr * N + c], csm);
        __syncthreads();
        if (tid < 128) {
            atomicAdd(&rowsum[zr * N + m0 + tid], srow[tid]);
            atomicAdd(&mrow[zr * N + m0 + tid], srowm[tid]);
        }
    } else {
        if (MODE == 1) {
            if (tid < 128) srow[tid] = 0.f;
            __syncthreads();
        }
        float ss[4][2];
        #pragma unroll
        for (int mi = 0; mi < 4; mi++) { ss[mi][0] = 0.f; ss[mi][1] = 0.f; }
        #pragma unroll
        for (int mi = 0; mi < 4; mi++) {
            int r0 = m0 + wm + mi * 16 + g;
            #pragma unroll
            for (int ni = 0; ni < 4; ni++) {
                int c = n0 + wn + ni * 8 + t4 * 2;
                float2 bc = *(const float2*)&bias[c];
                float v0 = acc[mi][ni][0] + bc.x;
                float v1 = acc[mi][ni][1] + bc.y;
                float v2 = acc[mi][ni][2] + bc.x;
                float v3 = acc[mi][ni][3] + bc.y;
                if (MODE == 0) {
                    v0 = (v0 > 0.f) ? v0 : expm1f(v0);
                    v1 = (v1 > 0.f) ? v1 : expm1f(v1);
                    v2 = (v2 > 0.f) ? v2 : expm1f(v2);
                    v3 = (v3 > 0.f) ? v3 : expm1f(v3);
                } else {
                    ss[mi][0] += v0 * v0 + v1 * v1;
                    ss[mi][1] += v2 * v2 + v3 * v3;
                }
                *(uint32_t*)&C[(size_t)r0 * Nc + c] = bf2_pack(v0, v1);
                *(uint32_t*)&C[(size_t)(r0 + 8) * Nc + c] = bf2_pack(v2, v3);
            }
        }
        if (MODE == 1) {
            #pragma unroll
            for (int mi = 0; mi < 4; mi++) {
                int r = wm + mi * 16 + g;
                atomicAdd(&srow[r], ss[mi][0]);
                atomicAdd(&srow[r + 8], ss[mi][1]);
            }
            __syncthreads();
            if (tid < 128) atomicAdd(&norms[m0 + tid], srow[tid]);
        }
    }
}

// ---------------- small utility kernels ------------------------------------
__global__ void zero_all_k(double* s, float* n2, float* a, float* b, float* c, float* d) {
    int i = blockIdx.x * blockDim.x + threadIdx.x;
    if (i < 4) s[i] = 0.0;
    if (i < 4 * N) n2[i] = 0.f;
    if (i < 2 * N) { a[i] = 0.f; b[i] = 0.f; c[i] = 0.f; d[i] = 0.f; }
}

// convert both weight matrices in one launch
__global__ void conv_w2_k(const float* __restrict__ w1, const float* __restrict__ w2,
                          __nv_bfloat16* __restrict__ d1, __nv_bfloat16* __restrict__ d2) {
    int idx = (blockIdx.x * blockDim.x + threadIdx.x) * 4;
    if (idx < D * D) {
        float4 a = *(const float4*)&w1[idx];
        float4 b = *(const float4*)&w2[idx];
        *(__nv_bfloat162*)&d1[idx] = __floats2bfloat162_rn(a.x, a.y);
        *(__nv_bfloat162*)&d1[idx + 2] = __floats2bfloat162_rn(a.z, a.w);
        *(__nv_bfloat162*)&d2[idx] = __floats2bfloat162_rn(b.x, b.y);
        *(__nv_bfloat162*)&d2[idx + 2] = __floats2bfloat162_rn(b.z, b.w);
    }
}

// convert 4 inputs to bf16 (stacked) AND emit combined bf16 z1/z2 in one pass
__global__ void conv4_combine_k(const float* __restrict__ a, const float* __restrict__ b,
                                const float* __restrict__ c, const float* __restrict__ d,
                                const float* __restrict__ gamma,
                                __nv_bfloat16* __restrict__ dst,
                                __nv_bfloat16* __restrict__ z1, __nv_bfloat16* __restrict__ z2) {
    float gm = *gamma;
    int idx = (blockIdx.x * blockDim.x + threadIdx.x) * 4;
    if (idx < N * D) {
        float4 v0 = *(const float4*)&a[idx];
        float4 v1 = *(const float4*)&b[idx];
        float4 v2 = *(const float4*)&c[idx];
        float4 v3 = *(const float4*)&d[idx];
        __nv_bfloat16* o0 = dst + idx;
        __nv_bfloat16* o1 = dst + (size_t)N * D + idx;
        __nv_bfloat16* o2 = dst + (size_t)2 * N * D + idx;
        __nv_bfloat16* o3 = dst + (size_t)3 * N * D + idx;
        *(__nv_bfloat162*)&o0[0] = __floats2bfloat162_rn(v0.x, v0.y);
        *(__nv_bfloat162*)&o0[2] = __floats2bfloat162_rn(v0.z, v0.w);
        *(__nv_bfloat162*)&o1[0] = __floats2bfloat162_rn(v1.x, v1.y);
        *(__nv_bfloat162*)&o1[2] = __floats2bfloat162_rn(v1.z, v1.w);
        *(__nv_bfloat162*)&o2[0] = __floats2bfloat162_rn(v2.x, v2.y);
        *(__nv_bfloat162*)&o2[2] = __floats2bfloat162_rn(v2.z, v2.w);
        *(__nv_bfloat162*)&o3[0] = __floats2bfloat162_rn(v3.x, v3.y);
        *(__nv_bfloat162*)&o3[2] = __floats2bfloat162_rn(v3.z, v3.w);
        float og = 1.f - gm;
        *(__nv_bfloat162*)&z1[idx]     = __floats2bfloat162_rn(og*v0.x + gm*v1.x, og*v0.y + gm*v1.y);
        *(__nv_bfloat162*)&z1[idx + 2] = __floats2bfloat162_rn(og*v0.z + gm*v1.z, og*v0.w + gm*v1.w);
        *(__nv_bfloat162*)&z2[idx]     = __floats2bfloat162_rn(og*v2.x + gm*v3.x, og*v2.y + gm*v3.y);
        *(__nv_bfloat162*)&z2[idx + 2] = __floats2bfloat162_rn(og*v2.z + gm*v3.z, og*v2.w + gm*v3.w);
    }
}

// ---------------- lori reduction over both passes (2N entries) -------------
__global__ void lori_reduce_k(const float* __restrict__ mrow, const float* __restrict__ rowsum,
                              const float* __restrict__ mcol, const float* __restrict__ colsum,
                              double* __restrict__ s) {
    __shared__ float sm[8];
    int i = blockIdx.x * blockDim.x + threadIdx.x;   // 0 .. 2N-1, block spans one half only
    float v = 0.f;
    if (i < 2 * N)
        v = logf(mrow[i]) - logf(rowsum[i] + 1e-8f)
          + logf(mcol[i]) - logf(colsum[i] + 1e-8f);
    #pragma unroll
    for (int o = 16; o; o >>= 1) v += __shfl_xor_sync(0xffffffffu, v, o);
    int lane = threadIdx.x & 31, w = threadIdx.x >> 5;
    if (lane == 0) sm[w] = v;
    __syncthreads();
    if (threadIdx.x < 8) {
        float t = sm[threadIdx.x];
        #pragma unroll
        for (int o = 4; o; o >>= 1) t += __shfl_xor_sync(0xffu, t, o);
        if (threadIdx.x == 0)
            atomicAdd(&s[(blockIdx.x * blockDim.x) >= N ? 1 : 0], (double)t);
    }
}

// ---------------- InfoNCE LSE over 100 pseudo-random negatives -------------
__global__ __launch_bounds__(128)
void neg_lse_k(const __nv_bfloat16* __restrict__ z1, const __nv_bfloat16* __restrict__ z2,
               const float* __restrict__ md, float* __restrict__ lse) {
    __shared__ float2 zrow[D / 2];
    __shared__ int idxs[NUM_NEG + 32];
    __shared__ float vals[NUM_NEG];
    int i = blockIdx.x;
    const __nv_bfloat162* zi = (const __nv_bfloat162*)(z1 + (size_t)i * D);
    for (int d = threadIdx.x; d < D / 2; d += blockDim.x)
        zrow[d] = __bfloat1622float2(zi[d]);
    int warp = threadIdx.x >> 5, lane = threadIdx.x & 31;
    if (warp == 0) {
        // warp-parallel selection of first NUM_NEG unmasked candidates (t-order)
        const float* mr = md + (size_t)i * N;
        unsigned start = ((unsigned)i * 2654435761u) & (N - 1);
        int cnt = 0;
        unsigned t = 0;
        while (cnt < NUM_NEG) {
            int c = (int)((start + (t + lane) * 97u) & (N - 1));
            float mv = mr[c];
            unsigned bal = __ballot_sync(0xffffffffu, mv == 0.f);
            int prefix = __popc(bal & ((1u << lane) - 1));
            if (mv == 0.f && cnt + prefix < NUM_NEG + 32) idxs[cnt + prefix] = c;
            cnt += __popc(bal);
            t += 32;
        }
    }
    __syncthreads();
    for (int k = warp; k < NUM_NEG; k += 4) {
        const __nv_bfloat162* zc = (const __nv_bfloat162*)(z2 + (size_t)idxs[k] * D);
        float s = 0.f;
        #pragma unroll 4
        for (int d = lane; d < D / 2; d += 32) {
            float2 x = zrow[d];
            float2 y = __bfloat1622float2(zc[d]);
            s = fmaf(x.x, y.x, s);
            s = fmaf(x.y, y.y, s);
        }
        #pragma unroll
        for (int o = 16; o; o >>= 1) s += __shfl_xor_sync(0xffffffffu, s, o);
        if (lane == 0) vals[k] = s;
    }
    __syncthreads();
    if (threadIdx.x == 0) {
        float m = -1e30f;
        for (int k = 0; k < NUM_NEG; k++) m = fmaxf(m, vals[k]);
        float ss = 0.f;
        for (int k = 0; k < NUM_NEG; k++) ss += __expf((vals[k] - m) * 10.0f);
        lse[i] = m * 10.0f + logf(ss);   // 1/INFONCE_TAU = 10
    }
}

// ---------------- InfoNCE positive pairs (warp per row, float4 mask scan) --
__global__ void inf_pairs_k(const __nv_bfloat16* __restrict__ z1, const __nv_bfloat16* __restrict__ z2,
                            const float* __restrict__ md, const float* __restrict__ lse,
                            double* __restrict__ s) {
    int warp = (blockIdx.x * blockDim.x + threadIdx.x) >> 5;
    int lane = threadIdx.x & 31;
    if (warp >= N) return;
    int i = warp;
    const float* mr = md + (size_t)i * N;
    const __nv_bfloat162* Zi = (const __nv_bfloat162*)(z1 + (size_t)i * D);
    float2 zi[16];
    #pragma unroll
    for (int u = 0; u < 16; u++) zi[u] = __bfloat1622float2(Zi[lane + u * 32]);
    float L = lse[i];
    float sum = 0.f;
    int cnt = 0;
    for (int jb = 0; jb < N; jb += 128) {
        float4 pv4 = *(const float4*)&mr[jb + lane * 4];
        float pvq[4] = {pv4.x, pv4.y, pv4.z, pv4.w};
        #pragma unroll
        for (int q = 0; q < 4; q++) {
            unsigned mask = __ballot_sync(0xffffffffu, pvq[q] > 0.f);
            while (mask) {
                int b = __ffs(mask) - 1;
                mask &= mask - 1;
                int j = jb + b * 4 + q;
                const __nv_bfloat162* Zj = (const __nv_bfloat162*)(z2 + (size_t)j * D);
                float dot = 0.f;
                #pragma unroll
                for (int u = 0; u < 16; u++) {
                    float2 y = __bfloat1622float2(Zj[lane + u * 32]);
                    dot = fmaf(zi[u].x, y.x, dot);
                    dot = fmaf(zi[u].y, y.y, dot);
                }
                #pragma unroll
                for (int o = 16; o; o >>= 1) dot += __shfl_xor_sync(0xffffffffu, dot, o);
                float p = dot * 10.0f;
                float mx = fmaxf(p, L);
                float pp = mx + logf(__expf(p - mx) + __expf(L - mx)) - p;
                sum += pp;
                cnt++;
            }
        }
    }
    if (lane == 0) {
        atomicAdd(&s[2], (double)sum);
        atomicAdd(&s[3], (double)cnt);
    }
}

// ---------------- finalize --------------------------------------------------
__global__ void finalize_k(float* out, const double* s) {
    double gcl = -0.5 * (s[0] + s[1]) / (double)N;
    out[0] = (float)(gcl + s[2] / s[3]);
}

// ---------------- launcher --------------------------------------------------
extern "C" void kernel_launch(void* const* d_in, const int* in_sizes, int n_in,
                              void* d_out, int out_size) {
    const float* z_mp1 = (const float*)d_in[0];
    const float* z_sc1 = (const float*)d_in[1];
    const float* pos1  = (const float*)d_in[2];
    const float* z_mp2 = (const float*)d_in[3];
    const float* z_sc2 = (const float*)d_in[4];
    const float* pos2  = (const float*)d_in[5];
    const float* md    = (const float*)d_in[6];
    const float* gamma = (const float*)d_in[7];
    const float* W1 = (const float*)d_in[8];
    const float* b1 = (const float*)d_in[9];
    const float* W2 = (const float*)d_in[10];
    const float* b2 = (const float*)d_in[11];
    float* out = (float*)d_out;

    __nv_bfloat16 *gZ, *gH, *gP, *gW1, *gW2, *gz1, *gz2;
    float *gn2, *grow, *gcol, *gmr, *gmc, *glse;
    double* gs;
    cudaGetSymbolAddress((void**)&gZ, g_Zall);
    cudaGetSymbolAddress((void**)&gH, g_Hall);
    cudaGetSymbolAddress((void**)&gP, g_Pall);
    cudaGetSymbolAddress((void**)&gW1, g_W1bf);
    cudaGetSymbolAddress((void**)&gW2, g_W2bf);
    cudaGetSymbolAddress((void**)&gz1, g_z1);
    cudaGetSymbolAddress((void**)&gz2, g_z2);
    cudaGetSymbolAddress((void**)&gn2, g_norm2);
    cudaGetSymbolAddress((void**)&grow, g_rowsum);
    cudaGetSymbolAddress((void**)&gcol, g_colsum);
    cudaGetSymbolAddress((void**)&gmr, g_mrow);
    cudaGetSymbolAddress((void**)&gmc, g_mcol);
    cudaGetSymbolAddress((void**)&glse, g_lse);
    cudaGetSymbolAddress((void**)&gs, g_s);

    cudaFuncSetAttribute(mm_bf16_k<0>, cudaFuncAttributeMaxDynamicSharedMemorySize, DSMEM);
    cudaFuncSetAttribute(mm_bf16_k<1>, cudaFuncAttributeMaxDynamicSharedMemorySize, DSMEM);
    cudaFuncSetAttribute(mm_bf16_k<2>, cudaFuncAttributeMaxDynamicSharedMemorySize, DSMEM);

    zero_all_k<<<(4 * N + 255) / 256, 256>>>(gs, gn2, grow, gcol, gmr, gmc);
    conv_w2_k<<<(D * D / 4 + 255) / 256, 256>>>(W1, W2, gW1, gW2);
    conv4_combine_k<<<(N * D / 4 + 255) / 256, 256>>>(z_mp1, z_sc1, z_mp2, z_sc2, gamma, gZ, gz1, gz2);

    // batched projection MLP: layer1 (ELU) then layer2 (+ row sumsq), M = 16384
    dim3 gproj(D / 128, 4 * N / 128);      // (8, 128)
    mm_bf16_k<0><<<gproj, 256, DSMEM>>>(gZ, gW1, b1, gH, nullptr, nullptr, nullptr, nullptr, nullptr, nullptr, nullptr, D);
    mm_bf16_k<1><<<gproj, 256, DSMEM>>>(gH, gW2, b2, gP, nullptr, nullptr, gn2, nullptr, nullptr, nullptr, nullptr, D);

    // both sim passes in one launch (z = pass index), inverse-norm rescale inside
    dim3 gsim(N / 128, N / 128, 2);        // (32, 32, 2)
    mm_bf16_k<2><<<gsim, 256, DSMEM>>>(gP, nullptr, nullptr, nullptr, pos1, pos2, gn2,
                                       grow, gcol, gmr, gmc, N);
    lori_reduce_k<<<2 * N / 256, 256>>>(gmr, grow, gmc, gcol, gs);

    neg_lse_k<<<N, 128>>>(gz1, gz2, md, glse);
    inf_pairs_k<<<N / 8, 256>>>(gz1, gz2, md, glse, gs);
    finalize_k<<<1, 1>>>(out, gs);
}

// round 15
// speedup vs baseline: 2.0555x; 1.0822x over previous
#include <cuda_runtime.h>
#include <cuda_fp16.h>
#include <cstdint>
#include <math.h>

#define N 4096
#define D 1024
#define NUM_NEG 100
#define NT 16            // K=1024 / 64
#define STAGE_BYTES 32768
#define DSMEM 98304      // 3 stages x 32KB (epilogue et overlaps)

// ---------------- scratch (device globals; no allocation allowed) ----------
__device__ __half g_Zall[4 * N * D];
__device__ __half g_Hall[4 * N * D];
__device__ __half g_Pall[4 * N * D];   // unnormalized projections
__device__ __half g_W1h[D * D];
__device__ __half g_W2h[D * D];
__device__ __half g_z1[N * D];
__device__ __half g_z2[N * D];
__device__ float g_norm2[4 * N];       // per-row sum of squares of P
__device__ float g_rowsum[2 * N], g_colsum[2 * N], g_mrow[2 * N], g_mcol[2 * N];
__device__ double g_s[4];  // [0]=gcl1 logsum, [1]=gcl2 logsum, [2]=pair_sum, [3]=pair_cnt

// ---------------- helpers ---------------------------------------------------
__device__ __forceinline__ uint32_t h2_pack(float a, float b) {
    __half2 t = __floats2half2_rn(a, b);
    return *reinterpret_cast<uint32_t*>(&t);
}

__device__ __forceinline__ float2 h2_unpack(uint32_t v) {
    return __half22float2(*reinterpret_cast<__half2*>(&v));
}

// fp16-accumulate HMMA
__device__ __forceinline__ void mma16816h(uint32_t* c, const uint32_t* a, const uint32_t* b) {
    asm volatile(
        "mma.sync.aligned.m16n8k16.row.col.f16.f16.f16.f16 "
        "{%0,%1}, {%2,%3,%4,%5}, {%6,%7}, {%0,%1};"
        : "+r"(c[0]), "+r"(c[1])
        : "r"(a[0]), "r"(a[1]), "r"(a[2]), "r"(a[3]), "r"(b[0]), "r"(b[1]));
}

__device__ __forceinline__ void ldsm4(uint32_t* r, uint32_t saddr) {
    asm volatile("ldmatrix.sync.aligned.m8n8.x4.shared.b16 {%0,%1,%2,%3}, [%4];"
                 : "=r"(r[0]), "=r"(r[1]), "=r"(r[2]), "=r"(r[3]) : "r"(saddr));
}

template <int W>
__device__ __forceinline__ void cpwait() {
    asm volatile("cp.async.wait_group %0;" :: "n"(W));
}

// swizzled byte offset inside a 128x64 fp16 stage tile (rows of 128B, 16B chunks)
__device__ __forceinline__ uint32_t SWZ64(int r, int ch) {
    return (uint32_t)(r * 128 + ((ch ^ (r & 7)) << 4));
}

// load one 64-K stage of A(128 rows) + B(128 rows), 256 threads
__device__ __forceinline__ void ld_stage(
    const __half* __restrict__ A, const __half* __restrict__ B,
    int m0, int n0, int kt, uint32_t st, int tid) {
    #pragma unroll
    for (int i = 0; i < 4; i++) {
        int idx = tid + i * 256;
        int row = idx >> 3, ch = idx & 7;
        const __half* g = &A[(size_t)(m0 + row) * D + kt + ch * 8];
        asm volatile("cp.async.cg.shared.global [%0], [%1], 16;"
                     :: "r"(st + SWZ64(row, ch)), "l"(g));
    }
    #pragma unroll
    for (int i = 0; i < 4; i++) {
        int idx = tid + i * 256;
        int row = idx >> 3, ch = idx & 7;
        const __half* g = &B[(size_t)(n0 + row) * D + kt + ch * 8];
        asm volatile("cp.async.cg.shared.global [%0], [%1], 16;"
                     :: "r"(st + 16384 + SWZ64(row, ch)), "l"(g));
    }
}

// ---------------- fp16 HMMA NT GEMM (fp16 accumulate) -----------------------
// C[i,j] = sum_k A[i,k]*B[j,k].
// MODE 0: +bias+ELU->fp16
// MODE 1: +bias->fp16, accumulate per-row sum-of-squares into norms[]
// MODE 2: sim epilogue w/ inverse-norm rescale, blockIdx.z selects pass
template <int MODE>
__global__ __launch_bounds__(256, 2)
void mm_h_k(const __half* __restrict__ Abase, const __half* __restrict__ Bbase,
            const float* __restrict__ bias, __half* __restrict__ C,
            const float* __restrict__ pos1, const float* __restrict__ pos2,
            float* __restrict__ norms,
            float* __restrict__ rowsum, float* __restrict__ colsum,
            float* __restrict__ mrow, float* __restrict__ mcol, int Nc) {
    extern __shared__ __align__(16) char dsm[];
    __shared__ float srow[128], srowm[128];
    __shared__ float sinvA[128], sinvB[128];

    int tid = threadIdx.x;
    int warp = tid >> 5, lane = tid & 31;
    int g = lane >> 2, t4 = lane & 3;
    int wm = (warp >> 2) * 64;   // 2 warp-rows x 64
    int wn = (warp & 3) * 32;    // 4 warp-cols x 32
    int m0 = blockIdx.y * 128, n0 = blockIdx.x * 128;
    int zr = blockIdx.z;
    const __half* A = Abase;
    const __half* B = Bbase;
    const float* pos = pos1;
    if (MODE == 2) {
        A = Abase + (size_t)(2 * zr) * N * D;
        B = Abase + (size_t)(2 * zr + 1) * N * D;
        pos = (zr == 0) ? pos1 : pos2;
    }
    uint32_t sb = (uint32_t)__cvta_generic_to_shared(dsm);

    uint32_t acc[4][4][2] = {};   // fp16x2 accumulators

    ld_stage(A, B, m0, n0, 0, sb, tid);
    asm volatile("cp.async.commit_group;");
    ld_stage(A, B, m0, n0, 64, sb + STAGE_BYTES, tid);
    asm volatile("cp.async.commit_group;");

    int lr = lane & 15, lc = lane >> 4;
    for (int s = 0; s < NT; s++) {
        if (s < NT - 1) cpwait<1>(); else cpwait<0>();
        __syncthreads();
        if (s + 2 < NT) {
            ld_stage(A, B, m0, n0, (s + 2) * 64, sb + ((s + 2) % 3) * STAGE_BYTES, tid);
            asm volatile("cp.async.commit_group;");
        }
        uint32_t ab = sb + (s % 3) * STAGE_BYTES;
        uint32_t bb = ab + 16384;
        #pragma unroll
        for (int ks = 0; ks < 4; ks++) {
            int ch = ks * 2 + lc;
            uint32_t a[4][4], b[2][4];
            #pragma unroll
            for (int mi = 0; mi < 4; mi++)
                ldsm4(a[mi], ab + SWZ64(wm + mi * 16 + lr, ch));
            #pragma unroll
            for (int nb = 0; nb < 2; nb++)
                ldsm4(b[nb], bb + SWZ64(wn + nb * 16 + lr, ch));
            #pragma unroll
            for (int mi = 0; mi < 4; mi++)
                #pragma unroll
                for (int ni = 0; ni < 4; ni++) {
                    uint32_t bf[2] = { b[ni >> 1][ni & 1], b[ni >> 1][(ni & 1) + 2] };
                    mma16816h(acc[mi][ni], a[mi], bf);
                }
        }
    }
    __syncthreads();   // smem reuse barrier (MODE 2 epilogue overlays stage bufs)

    if (MODE == 2) {
        if (tid < 128) {
            srow[tid] = 0.f; srowm[tid] = 0.f;
            sinvA[tid] = rsqrtf(norms[(size_t)(2 * zr) * N + m0 + tid]);
            sinvB[tid] = rsqrtf(norms[(size_t)(2 * zr + 1) * N + n0 + tid]);
        }
        __syncthreads();
        float ef[4][4][4];
        float rp[4][2] = {}, rpm[4][2] = {};
        #pragma unroll
        for (int mi = 0; mi < 4; mi++) {
            int rl0 = wm + mi * 16 + g;
            int r0 = m0 + rl0;
            int r1 = r0 + 8;
            float ia0 = sinvA[rl0] * 1.25f;       // fold 1/TAU
            float ia1 = sinvA[rl0 + 8] * 1.25f;
            #pragma unroll
            for (int ni = 0; ni < 4; ni++) {
                int cl = wn + ni * 8 + t4 * 2;
                int c = n0 + cl;
                float ib0 = sinvB[cl], ib1 = sinvB[cl + 1];
                float2 lo = h2_unpack(acc[mi][ni][0]);   // rows g: c, c+1
                float2 hi = h2_unpack(acc[mi][ni][1]);   // rows g+8: c, c+1
                float e0 = __expf(lo.x * ia0 * ib0);
                float e1 = __expf(lo.y * ia0 * ib1);
                float e2 = __expf(hi.x * ia1 * ib0);
                float e3 = __expf(hi.y * ia1 * ib1);
                ef[mi][ni][0] = e0; ef[mi][ni][1] = e1;
                ef[mi][ni][2] = e2; ef[mi][ni][3] = e3;
                float2 p0 = *(const float2*)&pos[(size_t)r0 * N + c];
                float2 p1 = *(const float2*)&pos[(size_t)r1 * N + c];
                rp[mi][0] += e0 + e1;            rp[mi][1] += e2 + e3;
                rpm[mi][0] += e0 * p0.x + e1 * p0.y;
                rpm[mi][1] += e2 * p1.x + e3 * p1.y;
            }
        }
        #pragma unroll
        for (int mi = 0; mi < 4; mi++) {
            int r = wm + mi * 16 + g;
            atomicAdd(&srow[r], rp[mi][0]);
            atomicAdd(&srow[r + 8], rp[mi][1]);
            atomicAdd(&srowm[r], rpm[mi][0]);
            atomicAdd(&srowm[r + 8], rpm[mi][1]);
        }
        // transpose e-tile into smem: et[col_local][row_local], pitch 65
        float* et = (float*)dsm + warp * (32 * 65);
        #pragma unroll
        for (int mi = 0; mi < 4; mi++)
            #pragma unroll
            for (int ni = 0; ni < 4; ni++)
                #pragma unroll
                for (int q = 0; q < 4; q++) {
                    int rl = mi * 16 + g + ((q >= 2) ? 8 : 0);
                    int cl = ni * 8 + t4 * 2 + (q & 1);
                    et[cl * 65 + rl] = ef[mi][ni][q];
                }
        __syncwarp();
        // lane owns one column; pos column read is contiguous
        int c = n0 + wn + lane;
        const float4* pc = (const float4*)&pos[(size_t)c * N + m0 + wm];
        float cs = 0.f, csm = 0.f;
        #pragma unroll
        for (int q = 0; q < 16; q++) {
            float4 m4 = pc[q];
            float a0 = et[lane * 65 + q * 4 + 0];
            float a1 = et[lane * 65 + q * 4 + 1];
            float a2 = et[lane * 65 + q * 4 + 2];
            float a3 = et[lane * 65 + q * 4 + 3];
            cs  += a0 + a1 + a2 + a3;
            csm += a0 * m4.x + a1 * m4.y + a2 * m4.z + a3 * m4.w;
        }
        atomicAdd(&colsum[zr * N + c], cs);
        atomicAdd(&mcol[zr * N + c], csm);
        __syncthreads();
        if (tid < 128) {
            atomicAdd(&rowsum[zr * N + m0 + tid], srow[tid]);
            atomicAdd(&mrow[zr * N + m0 + tid], srowm[tid]);
        }
    } else {
        if (MODE == 1) {
            if (tid < 128) srow[tid] = 0.f;
            __syncthreads();
        }
        float ss[4][2];
        #pragma unroll
        for (int mi = 0; mi < 4; mi++) { ss[mi][0] = 0.f; ss[mi][1] = 0.f; }
        #pragma unroll
        for (int mi = 0; mi < 4; mi++) {
            int r0 = m0 + wm + mi * 16 + g;
            #pragma unroll
            for (int ni = 0; ni < 4; ni++) {
                int c = n0 + wn + ni * 8 + t4 * 2;
                float2 bc = *(const float2*)&bias[c];
                float2 lo = h2_unpack(acc[mi][ni][0]);
                float2 hi = h2_unpack(acc[mi][ni][1]);
                float v0 = lo.x + bc.x;
                float v1 = lo.y + bc.y;
                float v2 = hi.x + bc.x;
                float v3 = hi.y + bc.y;
                if (MODE == 0) {
                    v0 = (v0 > 0.f) ? v0 : expm1f(v0);
                    v1 = (v1 > 0.f) ? v1 : expm1f(v1);
                    v2 = (v2 > 0.f) ? v2 : expm1f(v2);
                    v3 = (v3 > 0.f) ? v3 : expm1f(v3);
                } else {
                    ss[mi][0] += v0 * v0 + v1 * v1;
                    ss[mi][1] += v2 * v2 + v3 * v3;
                }
                *(uint32_t*)&C[(size_t)r0 * Nc + c] = h2_pack(v0, v1);
                *(uint32_t*)&C[(size_t)(r0 + 8) * Nc + c] = h2_pack(v2, v3);
            }
        }
        if (MODE == 1) {
            #pragma unroll
            for (int mi = 0; mi < 4; mi++) {
                int r = wm + mi * 16 + g;
                atomicAdd(&srow[r], ss[mi][0]);
                atomicAdd(&srow[r + 8], ss[mi][1]);
            }
            __syncthreads();
            if (tid < 128) atomicAdd(&norms[m0 + tid], srow[tid]);
        }
    }
}

// ---------------- small utility kernels ------------------------------------
__global__ void zero_all_k(double* s, float* n2, float* a, float* b, float* c, float* d) {
    int i = blockIdx.x * blockDim.x + threadIdx.x;
    if (i < 4) s[i] = 0.0;
    if (i < 4 * N) n2[i] = 0.f;
    if (i < 2 * N) { a[i] = 0.f; b[i] = 0.f; c[i] = 0.f; d[i] = 0.f; }
}

// convert both weight matrices in one launch
__global__ void conv_w2_k(const float* __restrict__ w1, const float* __restrict__ w2,
                          __half* __restrict__ d1, __half* __restrict__ d2) {
    int idx = (blockIdx.x * blockDim.x + threadIdx.x) * 4;
    if (idx < D * D) {
        float4 a = *(const float4*)&w1[idx];
        float4 b = *(const float4*)&w2[idx];
        *(uint32_t*)&d1[idx] = h2_pack(a.x, a.y);
        *(uint32_t*)&d1[idx + 2] = h2_pack(a.z, a.w);
        *(uint32_t*)&d2[idx] = h2_pack(b.x, b.y);
        *(uint32_t*)&d2[idx + 2] = h2_pack(b.z, b.w);
    }
}

// convert 4 inputs to fp16 (stacked) AND emit combined fp16 z1/z2 in one pass
__global__ void conv4_combine_k(const float* __restrict__ a, const float* __restrict__ b,
                                const float* __restrict__ c, const float* __restrict__ d,
                                const float* __restrict__ gamma,
                                __half* __restrict__ dst,
                                __half* __restrict__ z1, __half* __restrict__ z2) {
    float gm = *gamma;
    int idx = (blockIdx.x * blockDim.x + threadIdx.x) * 4;
    if (idx < N * D) {
        float4 v0 = *(const float4*)&a[idx];
        float4 v1 = *(const float4*)&b[idx];
        float4 v2 = *(const float4*)&c[idx];
        float4 v3 = *(const float4*)&d[idx];
        __half* o0 = dst + idx;
        __half* o1 = dst + (size_t)N * D + idx;
        __half* o2 = dst + (size_t)2 * N * D + idx;
        __half* o3 = dst + (size_t)3 * N * D + idx;
        *(uint32_t*)&o0[0] = h2_pack(v0.x, v0.y);
        *(uint32_t*)&o0[2] = h2_pack(v0.z, v0.w);
        *(uint32_t*)&o1[0] = h2_pack(v1.x, v1.y);
        *(uint32_t*)&o1[2] = h2_pack(v1.z, v1.w);
        *(uint32_t*)&o2[0] = h2_pack(v2.x, v2.y);
        *(uint32_t*)&o2[2] = h2_pack(v2.z, v2.w);
        *(uint32_t*)&o3[0] = h2_pack(v3.x, v3.y);
        *(uint32_t*)&o3[2] = h2_pack(v3.z, v3.w);
        float og = 1.f - gm;
        *(uint32_t*)&z1[idx]     = h2_pack(og*v0.x + gm*v1.x, og*v0.y + gm*v1.y);
        *(uint32_t*)&z1[idx + 2] = h2_pack(og*v0.z + gm*v1.z, og*v0.w + gm*v1.w);
        *(uint32_t*)&z2[idx]     = h2_pack(og*v2.x + gm*v3.x, og*v2.y + gm*v3.y);
        *(uint32_t*)&z2[idx + 2] = h2_pack(og*v2.z + gm*v3.z, og*v2.w + gm*v3.w);
    }
}

// ---------------- lori reduction over both passes (2N entries) -------------
__global__ void lori_reduce_k(const float* __restrict__ mrow, const float* __restrict__ rowsum,
                              const float* __restrict__ mcol, const float* __restrict__ colsum,
                              double* __restrict__ s) {
    __shared__ float sm[8];
    int i = blockIdx.x * blockDim.x + threadIdx.x;
    float v = 0.f;
    if (i < 2 * N)
        v = logf(mrow[i]) - logf(rowsum[i] + 1e-8f)
          + logf(mcol[i]) - logf(colsum[i] + 1e-8f);
    #pragma unroll
    for (int o = 16; o; o >>= 1) v += __shfl_xor_sync(0xffffffffu, v, o);
    int lane = threadIdx.x & 31, w = threadIdx.x >> 5;
    if (lane == 0) sm[w] = v;
    __syncthreads();
    if (threadIdx.x < 8) {
        float t = sm[threadIdx.x];
        #pragma unroll
        for (int o = 4; o; o >>= 1) t += __shfl_xor_sync(0xffu, t, o);
        if (threadIdx.x == 0)
            atomicAdd(&s[(blockIdx.x * blockDim.x) >= N ? 1 : 0], (double)t);
    }
}

// ---------------- InfoNCE fused: per-row LSE + positive pairs --------------
// one block (128 thr) per row: warp0 selects negatives, all warps dot,
// thread0 reduces lse, then 4 warps scan the mask quarters for positives
__global__ __launch_bounds__(128)
void infonce_k(const __half* __restrict__ z1, const __half* __restrict__ z2,
               const float* __restrict__ md, double* __restrict__ s) {
    __shared__ int idxs[NUM_NEG + 32];
    __shared__ float vals[NUM_NEG];
    __shared__ float sL;
    __shared__ float psum[4];
    __shared__ int pcnt[4];
    int i = blockIdx.x;
    int warp = threadIdx.x >> 5, lane = threadIdx.x & 31;
    const float* mr = md + (size_t)i * N;

    // z1 row into registers (lane-strided, identical across warps)
    const __half2* Zi = (const __half2*)(z1 + (size_t)i * D);
    float2 zi[16];
    #pragma unroll
    for (int u = 0; u < 16; u++) zi[u] = __half22float2(Zi[lane + u * 32]);

    if (warp == 0) {
        // warp-parallel selection of first NUM_NEG unmasked candidates (t-order)
        unsigned start = ((unsigned)i * 2654435761u) & (N - 1);
        int cnt = 0;
        unsigned t = 0;
        while (cnt < NUM_NEG) {
            int c = (int)((start + (t + lane) * 97u) & (N - 1));
            float mv = mr[c];
            unsigned bal = __ballot_sync(0xffffffffu, mv == 0.f);
            int prefix = __popc(bal & ((1u << lane) - 1));
            if (mv == 0.f && cnt + prefix < NUM_NEG + 32) idxs[cnt + prefix] = c;
            cnt += __popc(bal);
            t += 32;
        }
    }
    __syncthreads();
    for (int k = warp; k < NUM_NEG; k += 4) {
        const __half2* zc = (const __half2*)(z2 + (size_t)idxs[k] * D);
        float d = 0.f;
        #pragma unroll
        for (int u = 0; u < 16; u++) {
            float2 y = __half22float2(zc[lane + u * 32]);
            d = fmaf(zi[u].x, y.x, d);
            d = fmaf(zi[u].y, y.y, d);
        }
        #pragma unroll
        for (int o = 16; o; o >>= 1) d += __shfl_xor_sync(0xffffffffu, d, o);
        if (lane == 0) vals[k] = d;
    }
    __syncthreads();
    if (threadIdx.x == 0) {
        float m = -1e30f;
        for (int k = 0; k < NUM_NEG; k++) m = fmaxf(m, vals[k]);
        float ss = 0.f;
        for (int k = 0; k < NUM_NEG; k++) ss += __expf((vals[k] - m) * 10.0f);
        sL = m * 10.0f + logf(ss);   // 1/INFONCE_TAU = 10
    }
    __syncthreads();
    float L = sL;
    float sum = 0.f;
    int cnt = 0;
    // each warp scans one quarter of the mask row (float4 chunks)
    for (int jb = warp * (N / 4); jb < (warp + 1) * (N / 4); jb += 128) {
        float4 pv4 = *(const float4*)&mr[jb + lane * 4];
        float pvq[4] = {pv4.x, pv4.y, pv4.z, pv4.w};
        #pragma unroll
        for (int q = 0; q < 4; q++) {
            unsigned mask = __ballot_sync(0xffffffffu, pvq[q] > 0.f);
            while (mask) {
                int b = __ffs(mask) - 1;
                mask &= mask - 1;
                int j = jb + b * 4 + q;
                const __half2* Zj = (const __half2*)(z2 + (size_t)j * D);
                float dot = 0.f;
                #pragma unroll
                for (int u = 0; u < 16; u++) {
                    float2 y = __half22float2(Zj[lane + u * 32]);
                    dot = fmaf(zi[u].x, y.x, dot);
                    dot = fmaf(zi[u].y, y.y, dot);
                }
                #pragma unroll
                for (int o = 16; o; o >>= 1) dot += __shfl_xor_sync(0xffffffffu, dot, o);
                float p = dot * 10.0f;
                float mx = fmaxf(p, L);
                float pp = mx + logf(__expf(p - mx) + __expf(L - mx)) - p;
                sum += pp;
                cnt++;
            }
        }
    }
    if (lane == 0) { psum[warp] = sum; pcnt[warp] = cnt; }
    __syncthreads();
    if (threadIdx.x == 0) {
        atomicAdd(&s[2], (double)(psum[0] + psum[1] + psum[2] + psum[3]));
        atomicAdd(&s[3], (double)(pcnt[0] + pcnt[1] + pcnt[2] + pcnt[3]));
    }
}

// ---------------- finalize --------------------------------------------------
__global__ void finalize_k(float* out, const double* s) {
    double gcl = -0.5 * (s[0] + s[1]) / (double)N;
    out[0] = (float)(gcl + s[2] / s[3]);
}

// ---------------- launcher --------------------------------------------------
extern "C" void kernel_launch(void* const* d_in, const int* in_sizes, int n_in,
                              void* d_out, int out_size) {
    const float* z_mp1 = (const float*)d_in[0];
    const float* z_sc1 = (const float*)d_in[1];
    const float* pos1  = (const float*)d_in[2];
    const float* z_mp2 = (const float*)d_in[3];
    const float* z_sc2 = (const float*)d_in[4];
    const float* pos2  = (const float*)d_in[5];
    const float* md    = (const float*)d_in[6];
    const float* gamma = (const float*)d_in[7];
    const float* W1 = (const float*)d_in[8];
    const float* b1 = (const float*)d_in[9];
    const float* W2 = (const float*)d_in[10];
    const float* b2 = (const float*)d_in[11];
    float* out = (float*)d_out;

    __half *gZ, *gH, *gP, *gW1, *gW2, *gz1, *gz2;
    float *gn2, *grow, *gcol, *gmr, *gmc;
    double* gs;
    cudaGetSymbolAddress((void**)&gZ, g_Zall);
    cudaGetSymbolAddress((void**)&gH, g_Hall);
    cudaGetSymbolAddress((void**)&gP, g_Pall);
    cudaGetSymbolAddress((void**)&gW1, g_W1h);
    cudaGetSymbolAddress((void**)&gW2, g_W2h);
    cudaGetSymbolAddress((void**)&gz1, g_z1);
    cudaGetSymbolAddress((void**)&gz2, g_z2);
    cudaGetSymbolAddress((void**)&gn2, g_norm2);
    cudaGetSymbolAddress((void**)&grow, g_rowsum);
    cudaGetSymbolAddress((void**)&gcol, g_colsum);
    cudaGetSymbolAddress((void**)&gmr, g_mrow);
    cudaGetSymbolAddress((void**)&gmc, g_mcol);
    cudaGetSymbolAddress((void**)&gs, g_s);

    cudaFuncSetAttribute(mm_h_k<0>, cudaFuncAttributeMaxDynamicSharedMemorySize, DSMEM);
    cudaFuncSetAttribute(mm_h_k<1>, cudaFuncAttributeMaxDynamicSharedMemorySize, DSMEM);
    cudaFuncSetAttribute(mm_h_k<2>, cudaFuncAttributeMaxDynamicSharedMemorySize, DSMEM);

    zero_all_k<<<(4 * N + 255) / 256, 256>>>(gs, gn2, grow, gcol, gmr, gmc);
    conv_w2_k<<<(D * D / 4 + 255) / 256, 256>>>(W1, W2, gW1, gW2);
    conv4_combine_k<<<(N * D / 4 + 255) / 256, 256>>>(z_mp1, z_sc1, z_mp2, z_sc2, gamma, gZ, gz1, gz2);

    // batched projection MLP: layer1 (ELU) then layer2 (+ row sumsq), M = 16384
    dim3 gproj(D / 128, 4 * N / 128);      // (8, 128)
    mm_h_k<0><<<gproj, 256, DSMEM>>>(gZ, gW1, b1, gH, nullptr, nullptr, nullptr, nullptr, nullptr, nullptr, nullptr, D);
    mm_h_k<1><<<gproj, 256, DSMEM>>>(gH, gW2, b2, gP, nullptr, nullptr, gn2, nullptr, nullptr, nullptr, nullptr, D);

    // both sim passes in one launch (z = pass index), inverse-norm rescale inside
    dim3 gsim(N / 128, N / 128, 2);        // (32, 32, 2)
    mm_h_k<2><<<gsim, 256, DSMEM>>>(gP, nullptr, nullptr, nullptr, pos1, pos2, gn2,
                                    grow, gcol, gmr, gmc, N);
    lori_reduce_k<<<2 * N / 256, 256>>>(gmr, grow, gmc, gcol, gs);

    infonce_k<<<N, 128>>>(gz1, gz2, md, gs);
    finalize_k<<<1, 1>>>(out, gs);
}

// round 16
// speedup vs baseline: 2.1735x; 1.0574x over previous
#include <cuda_runtime.h>
#include <cuda_fp16.h>
#include <cstdint>
#include <math.h>

#define N 4096
#define D 1024
#define NUM_NEG 100
#define NT 16            // K=1024 / 64
#define STAGE_BYTES 32768
#define DSMEM 98304      // 3 stages x 32KB (epilogue et overlaps)

// ---------------- scratch (device globals; no allocation allowed) ----------
__device__ __half g_Zall[4 * N * D];
__device__ __half g_Hall[4 * N * D];
__device__ __half g_Pall[4 * N * D];   // unnormalized projections
__device__ __half g_W1h[D * D];
__device__ __half g_W2h[D * D];
__device__ __half g_z1[N * D];
__device__ __half g_z2[N * D];
__device__ float g_norm2[4 * N];       // per-row sum of squares of P
__device__ float g_rowsum[2 * N], g_colsum[2 * N], g_mrow[2 * N], g_mcol[2 * N];
__device__ double g_s[4];  // [0]=gcl1 logsum, [1]=gcl2 logsum, [2]=pair_sum, [3]=pair_cnt

// ---------------- helpers ---------------------------------------------------
__device__ __forceinline__ uint32_t h2_pack(float a, float b) {
    __half2 t = __floats2half2_rn(a, b);
    return *reinterpret_cast<uint32_t*>(&t);
}

__device__ __forceinline__ float2 h2_unpack(uint32_t v) {
    return __half22float2(*reinterpret_cast<__half2*>(&v));
}

// fp16-accumulate HMMA
__device__ __forceinline__ void mma16816h(uint32_t* c, const uint32_t* a, const uint32_t* b) {
    asm volatile(
        "mma.sync.aligned.m16n8k16.row.col.f16.f16.f16.f16 "
        "{%0,%1}, {%2,%3,%4,%5}, {%6,%7}, {%0,%1};"
        : "+r"(c[0]), "+r"(c[1])
        : "r"(a[0]), "r"(a[1]), "r"(a[2]), "r"(a[3]), "r"(b[0]), "r"(b[1]));
}

__device__ __forceinline__ void ldsm4(uint32_t* r, uint32_t saddr) {
    asm volatile("ldmatrix.sync.aligned.m8n8.x4.shared.b16 {%0,%1,%2,%3}, [%4];"
                 : "=r"(r[0]), "=r"(r[1]), "=r"(r[2]), "=r"(r[3]) : "r"(saddr));
}

template <int W>
__device__ __forceinline__ void cpwait() {
    asm volatile("cp.async.wait_group %0;" :: "n"(W));
}

// swizzled byte offset inside a 128x64 fp16 stage tile (rows of 128B, 16B chunks)
__device__ __forceinline__ uint32_t SWZ64(int r, int ch) {
    return (uint32_t)(r * 128 + ((ch ^ (r & 7)) << 4));
}

// ---------------- fp16 HMMA NT GEMM (fp16 accumulate) -----------------------
// C[i,j] = sum_k A[i,k]*B[j,k].
// MODE 0: +bias+ELU->fp16
// MODE 1: +bias->fp16, accumulate per-row sum-of-squares into norms[]
// MODE 2: sim epilogue w/ inverse-norm rescale, blockIdx.z selects pass
template <int MODE>
__global__ __launch_bounds__(256, 2)
void mm_h_k(const __half* __restrict__ Abase, const __half* __restrict__ Bbase,
            const float* __restrict__ bias, __half* __restrict__ C,
            const float* __restrict__ pos1, const float* __restrict__ pos2,
            float* __restrict__ norms,
            float* __restrict__ rowsum, float* __restrict__ colsum,
            float* __restrict__ mrow, float* __restrict__ mcol, int Nc) {
    extern __shared__ __align__(16) char dsm[];
    __shared__ float srow[128], srowm[128];
    __shared__ float sinvA[128], sinvB[128];

    int tid = threadIdx.x;
    int warp = tid >> 5, lane = tid & 31;
    int g = lane >> 2, t4 = lane & 3;
    int wm = (warp >> 2) * 64;   // 2 warp-rows x 64
    int wn = (warp & 3) * 32;    // 4 warp-cols x 32
    int m0 = blockIdx.y * 128, n0 = blockIdx.x * 128;
    int zr = blockIdx.z;
    const __half* A = Abase;
    const __half* B = Bbase;
    const float* pos = pos1;
    if (MODE == 2) {
        A = Abase + (size_t)(2 * zr) * N * D;
        B = Abase + (size_t)(2 * zr + 1) * N * D;
        pos = (zr == 0) ? pos1 : pos2;
    }
    uint32_t sb = (uint32_t)__cvta_generic_to_shared(dsm);

    // hoisted per-thread address algebra
    int lr = lane & 15, lc = lane >> 4;
    uint32_t rowA = (uint32_t)((wm + lr) * 128);            // A-row byte offset
    uint32_t rowB = 16384u + (uint32_t)((wn + lr) * 128);   // B-row byte offset
    uint32_t xoff[4];
    #pragma unroll
    for (int ks = 0; ks < 4; ks++)
        xoff[ks] = (uint32_t)(((ks * 2 + lc) ^ (lr & 7)) << 4);
    // cp.async per-thread store offsets (row = tid>>3 (+i*32), ch = tid&7)
    int ldrow = tid >> 3, ldch = tid & 7;
    uint32_t stoff[4];
    #pragma unroll
    for (int i = 0; i < 4; i++)
        stoff[i] = SWZ64(ldrow + i * 32, ldch);
    const __half* gA = &A[(size_t)(m0 + ldrow) * D + ldch * 8];
    const __half* gB = &B[(size_t)(n0 + ldrow) * D + ldch * 8];

    uint32_t acc[4][4][2] = {};   // fp16x2 accumulators

    #pragma unroll
    for (int p = 0; p < 2; p++) {
        uint32_t st = sb + p * STAGE_BYTES;
        #pragma unroll
        for (int i = 0; i < 4; i++) {
            asm volatile("cp.async.cg.shared.global [%0], [%1], 16;"
                         :: "r"(st + stoff[i]), "l"(gA + (size_t)(i * 32) * D + p * 64));
            asm volatile("cp.async.cg.shared.global [%0], [%1], 16;"
                         :: "r"(st + 16384u + stoff[i]), "l"(gB + (size_t)(i * 32) * D + p * 64));
        }
        asm volatile("cp.async.commit_group;");
    }

    #pragma unroll
    for (int s = 0; s < NT; s++) {
        if (s < NT - 1) cpwait<1>(); else cpwait<0>();
        __syncthreads();
        if (s + 2 < NT) {
            uint32_t st = sb + ((s + 2) % 3) * STAGE_BYTES;
            #pragma unroll
            for (int i = 0; i < 4; i++) {
                asm volatile("cp.async.cg.shared.global [%0], [%1], 16;"
                             :: "r"(st + stoff[i]), "l"(gA + (size_t)(i * 32) * D + (s + 2) * 64));
                asm volatile("cp.async.cg.shared.global [%0], [%1], 16;"
                             :: "r"(st + 16384u + stoff[i]), "l"(gB + (size_t)(i * 32) * D + (s + 2) * 64));
            }
            asm volatile("cp.async.commit_group;");
        }
        uint32_t ab = sb + (s % 3) * STAGE_BYTES + rowA;
        uint32_t bb = sb + (s % 3) * STAGE_BYTES + rowB;
        #pragma unroll
        for (int ks = 0; ks < 4; ks++) {
            uint32_t xo = xoff[ks];
            uint32_t a[4][4], b[2][4];
            #pragma unroll
            for (int mi = 0; mi < 4; mi++)
                ldsm4(a[mi], ab + mi * 2048 + xo);
            #pragma unroll
            for (int nb = 0; nb < 2; nb++)
                ldsm4(b[nb], bb + nb * 2048 + xo);
            #pragma unroll
            for (int mi = 0; mi < 4; mi++)
                #pragma unroll
                for (int ni = 0; ni < 4; ni++) {
                    uint32_t bf[2] = { b[ni >> 1][ni & 1], b[ni >> 1][(ni & 1) + 2] };
                    mma16816h(acc[mi][ni], a[mi], bf);
                }
        }
    }
    __syncthreads();   // smem reuse barrier (MODE 2 epilogue overlays stage bufs)

    if (MODE == 2) {
        if (tid < 128) {
            srow[tid] = 0.f; srowm[tid] = 0.f;
            sinvA[tid] = rsqrtf(norms[(size_t)(2 * zr) * N + m0 + tid]);
            sinvB[tid] = rsqrtf(norms[(size_t)(2 * zr + 1) * N + n0 + tid]);
        }
        __syncthreads();
        float ef[4][4][4];
        float rp[4][2] = {}, rpm[4][2] = {};
        #pragma unroll
        for (int mi = 0; mi < 4; mi++) {
            int rl0 = wm + mi * 16 + g;
            int r0 = m0 + rl0;
            int r1 = r0 + 8;
            float ia0 = sinvA[rl0] * 1.25f;       // fold 1/TAU
            float ia1 = sinvA[rl0 + 8] * 1.25f;
            #pragma unroll
            for (int ni = 0; ni < 4; ni++) {
                int cl = wn + ni * 8 + t4 * 2;
                int c = n0 + cl;
                float ib0 = sinvB[cl], ib1 = sinvB[cl + 1];
                float2 lo = h2_unpack(acc[mi][ni][0]);   // rows g: c, c+1
                float2 hi = h2_unpack(acc[mi][ni][1]);   // rows g+8: c, c+1
                float e0 = __expf(lo.x * ia0 * ib0);
                float e1 = __expf(lo.y * ia0 * ib1);
                float e2 = __expf(hi.x * ia1 * ib0);
                float e3 = __expf(hi.y * ia1 * ib1);
                ef[mi][ni][0] = e0; ef[mi][ni][1] = e1;
                ef[mi][ni][2] = e2; ef[mi][ni][3] = e3;
                float2 p0 = *(const float2*)&pos[(size_t)r0 * N + c];
                float2 p1 = *(const float2*)&pos[(size_t)r1 * N + c];
                rp[mi][0] += e0 + e1;            rp[mi][1] += e2 + e3;
                rpm[mi][0] += e0 * p0.x + e1 * p0.y;
                rpm[mi][1] += e2 * p1.x + e3 * p1.y;
            }
        }
        #pragma unroll
        for (int mi = 0; mi < 4; mi++) {
            int r = wm + mi * 16 + g;
            atomicAdd(&srow[r], rp[mi][0]);
            atomicAdd(&srow[r + 8], rp[mi][1]);
            atomicAdd(&srowm[r], rpm[mi][0]);
            atomicAdd(&srowm[r + 8], rpm[mi][1]);
        }
        // transpose e-tile into smem: et[col_local][row_local], pitch 65
        float* et = (float*)dsm + warp * (32 * 65);
        #pragma unroll
        for (int mi = 0; mi < 4; mi++)
            #pragma unroll
            for (int ni = 0; ni < 4; ni++)
                #pragma unroll
                for (int q = 0; q < 4; q++) {
                    int rl = mi * 16 + g + ((q >= 2) ? 8 : 0);
                    int cl = ni * 8 + t4 * 2 + (q & 1);
                    et[cl * 65 + rl] = ef[mi][ni][q];
                }
        __syncwarp();
        // lane owns one column; pos column read is contiguous
        int c = n0 + wn + lane;
        const float4* pc = (const float4*)&pos[(size_t)c * N + m0 + wm];
        float cs = 0.f, csm = 0.f;
        #pragma unroll
        for (int q = 0; q < 16; q++) {
            float4 m4 = pc[q];
            float a0 = et[lane * 65 + q * 4 + 0];
            float a1 = et[lane * 65 + q * 4 + 1];
            float a2 = et[lane * 65 + q * 4 + 2];
            float a3 = et[lane * 65 + q * 4 + 3];
            cs  += a0 + a1 + a2 + a3;
            csm += a0 * m4.x + a1 * m4.y + a2 * m4.z + a3 * m4.w;
        }
        atomicAdd(&colsum[zr * N + c], cs);
        atomicAdd(&mcol[zr * N + c], csm);
        __syncthreads();
        if (tid < 128) {
            atomicAdd(&rowsum[zr * N + m0 + tid], srow[tid]);
            atomicAdd(&mrow[zr * N + m0 + tid], srowm[tid]);
        }
    } else {
        if (MODE == 1) {
            if (tid < 128) srow[tid] = 0.f;
            __syncthreads();
        }
        float ss[4][2];
        #pragma unroll
        for (int mi = 0; mi < 4; mi++) { ss[mi][0] = 0.f; ss[mi][1] = 0.f; }
        #pragma unroll
        for (int mi = 0; mi < 4; mi++) {
            int r0 = m0 + wm + mi * 16 + g;
            #pragma unroll
            for (int ni = 0; ni < 4; ni++) {
                int c = n0 + wn + ni * 8 + t4 * 2;
                float2 bc = *(const float2*)&bias[c];
                float2 lo = h2_unpack(acc[mi][ni][0]);
                float2 hi = h2_unpack(acc[mi][ni][1]);
                float v0 = lo.x + bc.x;
                float v1 = lo.y + bc.y;
                float v2 = hi.x + bc.x;
                float v3 = hi.y + bc.y;
                if (MODE == 0) {
                    v0 = (v0 > 0.f) ? v0 : expm1f(v0);
                    v1 = (v1 > 0.f) ? v1 : expm1f(v1);
                    v2 = (v2 > 0.f) ? v2 : expm1f(v2);
                    v3 = (v3 > 0.f) ? v3 : expm1f(v3);
                } else {
                    ss[mi][0] += v0 * v0 + v1 * v1;
                    ss[mi][1] += v2 * v2 + v3 * v3;
                }
                *(uint32_t*)&C[(size_t)r0 * Nc + c] = h2_pack(v0, v1);
                *(uint32_t*)&C[(size_t)(r0 + 8) * Nc + c] = h2_pack(v2, v3);
            }
        }
        if (MODE == 1) {
            #pragma unroll
            for (int mi = 0; mi < 4; mi++) {
                int r = wm + mi * 16 + g;
                atomicAdd(&srow[r], ss[mi][0]);
                atomicAdd(&srow[r + 8], ss[mi][1]);
            }
            __syncthreads();
            if (tid < 128) atomicAdd(&norms[m0 + tid], srow[tid]);
        }
    }
}

// ---------------- small utility kernels ------------------------------------
__global__ void zero_all_k(double* s, float* n2, float* a, float* b, float* c, float* d) {
    int i = blockIdx.x * blockDim.x + threadIdx.x;
    if (i < 4) s[i] = 0.0;
    if (i < 4 * N) n2[i] = 0.f;
    if (i < 2 * N) { a[i] = 0.f; b[i] = 0.f; c[i] = 0.f; d[i] = 0.f; }
}

// convert both weight matrices in one launch
__global__ void conv_w2_k(const float* __restrict__ w1, const float* __restrict__ w2,
                          __half* __restrict__ d1, __half* __restrict__ d2) {
    int idx = (blockIdx.x * blockDim.x + threadIdx.x) * 4;
    if (idx < D * D) {
        float4 a = *(const float4*)&w1[idx];
        float4 b = *(const float4*)&w2[idx];
        *(uint32_t*)&d1[idx] = h2_pack(a.x, a.y);
        *(uint32_t*)&d1[idx + 2] = h2_pack(a.z, a.w);
        *(uint32_t*)&d2[idx] = h2_pack(b.x, b.y);
        *(uint32_t*)&d2[idx + 2] = h2_pack(b.z, b.w);
    }
}

// convert 4 inputs to fp16 (stacked) AND emit combined fp16 z1/z2 in one pass
__global__ void conv4_combine_k(const float* __restrict__ a, const float* __restrict__ b,
                                const float* __restrict__ c, const float* __restrict__ d,
                                const float* __restrict__ gamma,
                                __half* __restrict__ dst,
                                __half* __restrict__ z1, __half* __restrict__ z2) {
    float gm = *gamma;
    int idx = (blockIdx.x * blockDim.x + threadIdx.x) * 4;
    if (idx < N * D) {
        float4 v0 = *(const float4*)&a[idx];
        float4 v1 = *(const float4*)&b[idx];
        float4 v2 = *(const float4*)&c[idx];
        float4 v3 = *(const float4*)&d[idx];
        __half* o0 = dst + idx;
        __half* o1 = dst + (size_t)N * D + idx;
        __half* o2 = dst + (size_t)2 * N * D + idx;
        __half* o3 = dst + (size_t)3 * N * D + idx;
        *(uint32_t*)&o0[0] = h2_pack(v0.x, v0.y);
        *(uint32_t*)&o0[2] = h2_pack(v0.z, v0.w);
        *(uint32_t*)&o1[0] = h2_pack(v1.x, v1.y);
        *(uint32_t*)&o1[2] = h2_pack(v1.z, v1.w);
        *(uint32_t*)&o2[0] = h2_pack(v2.x, v2.y);
        *(uint32_t*)&o2[2] = h2_pack(v2.z, v2.w);
        *(uint32_t*)&o3[0] = h2_pack(v3.x, v3.y);
        *(uint32_t*)&o3[2] = h2_pack(v3.z, v3.w);
        float og = 1.f - gm;
        *(uint32_t*)&z1[idx]     = h2_pack(og*v0.x + gm*v1.x, og*v0.y + gm*v1.y);
        *(uint32_t*)&z1[idx + 2] = h2_pack(og*v0.z + gm*v1.z, og*v0.w + gm*v1.w);
        *(uint32_t*)&z2[idx]     = h2_pack(og*v2.x + gm*v3.x, og*v2.y + gm*v3.y);
        *(uint32_t*)&z2[idx + 2] = h2_pack(og*v2.z + gm*v3.z, og*v2.w + gm*v3.w);
    }
}

// ---------------- lori reduction over both passes (2N entries) -------------
__global__ void lori_reduce_k(const float* __restrict__ mrow, const float* __restrict__ rowsum,
                              const float* __restrict__ mcol, const float* __restrict__ colsum,
                              double* __restrict__ s) {
    __shared__ float sm[8];
    int i = blockIdx.x * blockDim.x + threadIdx.x;
    float v = 0.f;
    if (i < 2 * N)
        v = logf(mrow[i]) - logf(rowsum[i] + 1e-8f)
          + logf(mcol[i]) - logf(colsum[i] + 1e-8f);
    #pragma unroll
    for (int o = 16; o; o >>= 1) v += __shfl_xor_sync(0xffffffffu, v, o);
    int lane = threadIdx.x & 31, w = threadIdx.x >> 5;
    if (lane == 0) sm[w] = v;
    __syncthreads();
    if (threadIdx.x < 8) {
        float t = sm[threadIdx.x];
        #pragma unroll
        for (int o = 4; o; o >>= 1) t += __shfl_xor_sync(0xffu, t, o);
        if (threadIdx.x == 0)
            atomicAdd(&s[(blockIdx.x * blockDim.x) >= N ? 1 : 0], (double)t);
    }
}

// ---------------- InfoNCE fused: per-row LSE + positive pairs --------------
__global__ __launch_bounds__(128)
void infonce_k(const __half* __restrict__ z1, const __half* __restrict__ z2,
               const float* __restrict__ md, double* __restrict__ s) {
    __shared__ int idxs[NUM_NEG + 32];
    __shared__ float vals[NUM_NEG];
    __shared__ float sL;
    __shared__ float psum[4];
    __shared__ int pcnt[4];
    int i = blockIdx.x;
    int warp = threadIdx.x >> 5, lane = threadIdx.x & 31;
    const float* mr = md + (size_t)i * N;

    const __half2* Zi = (const __half2*)(z1 + (size_t)i * D);
    float2 zi[16];
    #pragma unroll
    for (int u = 0; u < 16; u++) zi[u] = __half22float2(Zi[lane + u * 32]);

    if (warp == 0) {
        unsigned start = ((unsigned)i * 2654435761u) & (N - 1);
        int cnt = 0;
        unsigned t = 0;
        while (cnt < NUM_NEG) {
            int c = (int)((start + (t + lane) * 97u) & (N - 1));
            float mv = mr[c];
            unsigned bal = __ballot_sync(0xffffffffu, mv == 0.f);
            int prefix = __popc(bal & ((1u << lane) - 1));
            if (mv == 0.f && cnt + prefix < NUM_NEG + 32) idxs[cnt + prefix] = c;
            cnt += __popc(bal);
            t += 32;
        }
    }
    __syncthreads();
    for (int k = warp; k < NUM_NEG; k += 4) {
        const __half2* zc = (const __half2*)(z2 + (size_t)idxs[k] * D);
        float d = 0.f;
        #pragma unroll
        for (int u = 0; u < 16; u++) {
            float2 y = __half22float2(zc[lane + u * 32]);
            d = fmaf(zi[u].x, y.x, d);
            d = fmaf(zi[u].y, y.y, d);
        }
        #pragma unroll
        for (int o = 16; o; o >>= 1) d += __shfl_xor_sync(0xffffffffu, d, o);
        if (lane == 0) vals[k] = d;
    }
    __syncthreads();
    if (threadIdx.x == 0) {
        float m = -1e30f;
        for (int k = 0; k < NUM_NEG; k++) m = fmaxf(m, vals[k]);
        float ss = 0.f;
        for (int k = 0; k < NUM_NEG; k++) ss += __expf((vals[k] - m) * 10.0f);
        sL = m * 10.0f + logf(ss);   // 1/INFONCE_TAU = 10
    }
    __syncthreads();
    float L = sL;
    float sum = 0.f;
    int cnt = 0;
    for (int jb = warp * (N / 4); jb < (warp + 1) * (N / 4); jb += 128) {
        float4 pv4 = *(const float4*)&mr[jb + lane * 4];
        float pvq[4] = {pv4.x, pv4.y, pv4.z, pv4.w};
        #pragma unroll
        for (int q = 0; q < 4; q++) {
            unsigned mask = __ballot_sync(0xffffffffu, pvq[q] > 0.f);
            while (mask) {
                int b = __ffs(mask) - 1;
                mask &= mask - 1;
                int j = jb + b * 4 + q;
                const __half2* Zj = (const __half2*)(z2 + (size_t)j * D);
                float dot = 0.f;
                #pragma unroll
                for (int u = 0; u < 16; u++) {
                    float2 y = __half22float2(Zj[lane + u * 32]);
                    dot = fmaf(zi[u].x, y.x, dot);
                    dot = fmaf(zi[u].y, y.y, dot);
                }
                #pragma unroll
                for (int o = 16; o; o >>= 1) dot += __shfl_xor_sync(0xffffffffu, dot, o);
                float p = dot * 10.0f;
                float mx = fmaxf(p, L);
                float pp = mx + logf(__expf(p - mx) + __expf(L - mx)) - p;
                sum += pp;
                cnt++;
            }
        }
    }
    if (lane == 0) { psum[warp] = sum; pcnt[warp] = cnt; }
    __syncthreads();
    if (threadIdx.x == 0) {
        atomicAdd(&s[2], (double)(psum[0] + psum[1] + psum[2] + psum[3]));
        atomicAdd(&s[3], (double)(pcnt[0] + pcnt[1] + pcnt[2] + pcnt[3]));
    }
}

// ---------------- finalize --------------------------------------------------
__global__ void finalize_k(float* out, const double* s) {
    double gcl = -0.5 * (s[0] + s[1]) / (double)N;
    out[0] = (float)(gcl + s[2] / s[3]);
}

// ---------------- launcher --------------------------------------------------
extern "C" void kernel_launch(void* const* d_in, const int* in_sizes, int n_in,
                              void* d_out, int out_size) {
    const float* z_mp1 = (const float*)d_in[0];
    const float* z_sc1 = (const float*)d_in[1];
    const float* pos1  = (const float*)d_in[2];
    const float* z_mp2 = (const float*)d_in[3];
    const float* z_sc2 = (const float*)d_in[4];
    const float* pos2  = (const float*)d_in[5];
    const float* md    = (const float*)d_in[6];
    const float* gamma = (const float*)d_in[7];
    const float* W1 = (const float*)d_in[8];
    const float* b1 = (const float*)d_in[9];
    const float* W2 = (const float*)d_in[10];
    const float* b2 = (const float*)d_in[11];
    float* out = (float*)d_out;

    __half *gZ, *gH, *gP, *gW1, *gW2, *gz1, *gz2;
    float *gn2, *grow, *gcol, *gmr, *gmc;
    double* gs;
    cudaGetSymbolAddress((void**)&gZ, g_Zall);
    cudaGetSymbolAddress((void**)&gH, g_Hall);
    cudaGetSymbolAddress((void**)&gP, g_Pall);
    cudaGetSymbolAddress((void**)&gW1, g_W1h);
    cudaGetSymbolAddress((void**)&gW2, g_W2h);
    cudaGetSymbolAddress((void**)&gz1, g_z1);
    cudaGetSymbolAddress((void**)&gz2, g_z2);
    cudaGetSymbolAddress((void**)&gn2, g_norm2);
    cudaGetSymbolAddress((void**)&grow, g_rowsum);
    cudaGetSymbolAddress((void**)&gcol, g_colsum);
    cudaGetSymbolAddress((void**)&gmr, g_mrow);
    cudaGetSymbolAddress((void**)&gmc, g_mcol);
    cudaGetSymbolAddress((void**)&gs, g_s);

    cudaFuncSetAttribute(mm_h_k<0>, cudaFuncAttributeMaxDynamicSharedMemorySize, DSMEM);
    cudaFuncSetAttribute(mm_h_k<1>, cudaFuncAttributeMaxDynamicSharedMemorySize, DSMEM);
    cudaFuncSetAttribute(mm_h_k<2>, cudaFuncAttributeMaxDynamicSharedMemorySize, DSMEM);

    zero_all_k<<<(4 * N + 255) / 256, 256>>>(gs, gn2, grow, gcol, gmr, gmc);
    conv_w2_k<<<(D * D / 4 + 255) / 256, 256>>>(W1, W2, gW1, gW2);
    conv4_combine_k<<<(N * D / 4 + 255) / 256, 256>>>(z_mp1, z_sc1, z_mp2, z_sc2, gamma, gZ, gz1, gz2);

    // batched projection MLP: layer1 (ELU) then layer2 (+ row sumsq), M = 16384
    dim3 gproj(D / 128, 4 * N / 128);      // (8, 128)
    mm_h_k<0><<<gproj, 256, DSMEM>>>(gZ, gW1, b1, gH, nullptr, nullptr, nullptr, nullptr, nullptr, nullptr, nullptr, D);
    mm_h_k<1><<<gproj, 256, DSMEM>>>(gH, gW2, b2, gP, nullptr, nullptr, gn2, nullptr, nullptr, nullptr, nullptr, D);

    // both sim passes in one launch (z = pass index), inverse-norm rescale inside
    dim3 gsim(N / 128, N / 128, 2);        // (32, 32, 2)
    mm_h_k<2><<<gsim, 256, DSMEM>>>(gP, nullptr, nullptr, nullptr, pos1, pos2, gn2,
                                    grow, gcol, gmr, gmc, N);
    lori_reduce_k<<<2 * N / 256, 256>>>(gmr, grow, gmc, gcol, gs);

    infonce_k<<<N, 128>>>(gz1, gz2, md, gs);
    finalize_k<<<1, 1>>>(out, gs);
}